// round 11
// baseline (speedup 1.0000x reference)
#include <cuda_runtime.h>
#include <cuda_fp16.h>
#include <math.h>
#include <stdint.h>

#define Bb 2
#define Tt 2048
#define Cc 1024
#define Hh 16
#define Dd 64
#define RMS_EPS 1.1920928955078125e-07f
// 0.125 * log2(e): folded into Q so QK^T scores are exp2-domain logits
#define QSCALE 0.1803368801111204f

// ---------------- scratch (allocation-free device globals) ----------------
__device__ __half g_Xhi[(size_t)4096*1024];
__device__ __half g_Xlo[(size_t)4096*1024];
__device__ __half g_Wh [(size_t)3072*1024];   // wq|wk|wv stacked rows, fp16
__device__ __half g_Ph [(size_t)1024*1024];   // w_proj fp16
__device__ __half g_Qh [(size_t)Bb*Hh*Tt*Dd];
__device__ __half g_Ql [(size_t)Bb*Hh*Tt*Dd];
__device__ __half g_Kh [(size_t)Bb*Hh*Tt*Dd];
__device__ __half g_Vh [(size_t)Bb*Hh*Tt*Dd];
__device__ __half g_Ohi[(size_t)4096*1024];   // attention out, [(b,t)][(h,d)]
__device__ __half g_Olo[(size_t)4096*1024];

// ---------------- helpers ----------------
__device__ __forceinline__ uint32_t smem_u32(const void* p) {
    uint32_t a;
    asm("{ .reg .u64 t; cvta.to.shared.u64 t, %1; cvt.u32.u64 %0, t; }" : "=r"(a) : "l"(p));
    return a;
}
__device__ __forceinline__ void cp16(uint32_t s, const void* g) {
    asm volatile("cp.async.cg.shared.global [%0], [%1], 16;" :: "r"(s), "l"(g));
}
#define CP_COMMIT() asm volatile("cp.async.commit_group;" ::: "memory")
#define CP_WAIT0()  asm volatile("cp.async.wait_group 0;" ::: "memory")
#define CP_WAIT1()  asm volatile("cp.async.wait_group 1;" ::: "memory")

__device__ __forceinline__ void ldsm4(uint32_t* r, uint32_t a) {
    asm volatile("ldmatrix.sync.aligned.m8n8.x4.shared.b16 {%0,%1,%2,%3}, [%4];"
                 : "=r"(r[0]), "=r"(r[1]), "=r"(r[2]), "=r"(r[3]) : "r"(a));
}
__device__ __forceinline__ void ldsm4t(uint32_t* r, uint32_t a) {
    asm volatile("ldmatrix.sync.aligned.m8n8.x4.trans.shared.b16 {%0,%1,%2,%3}, [%4];"
                 : "=r"(r[0]), "=r"(r[1]), "=r"(r[2]), "=r"(r[3]) : "r"(a));
}
__device__ __forceinline__ void mma_fp(float* d, const uint32_t* a, const uint32_t* b) {
    asm volatile(
        "mma.sync.aligned.m16n8k16.row.col.f32.f16.f16.f32 "
        "{%0,%1,%2,%3}, {%4,%5,%6,%7}, {%8,%9}, {%0,%1,%2,%3};"
        : "+f"(d[0]), "+f"(d[1]), "+f"(d[2]), "+f"(d[3])
        : "r"(a[0]), "r"(a[1]), "r"(a[2]), "r"(a[3]), "r"(b[0]), "r"(b[1]));
}
// raw ex2.approx (input already in log2 domain)
__device__ __forceinline__ float ex2(float x) {
    float r;
    asm("ex2.approx.f32 %0, %1;" : "=f"(r) : "f"(x));
    return r;
}
// split two fp32 into packed fp16x2 hi and lo words (elem a -> low half)
__device__ __forceinline__ void split2(float a, float b, uint32_t& h, uint32_t& l) {
    __half ah = __float2half_rn(a), bh = __float2half_rn(b);
    float al = a - __half2float(ah);
    float bl = b - __half2float(bh);
    __half hv[2] = {ah, bh};
    __half lv[2] = {__float2half_rn(al), __float2half_rn(bl)};
    h = *reinterpret_cast<uint32_t*>(hv);
    l = *reinterpret_cast<uint32_t*>(lv);
}

// ---------------- converts ----------------
__global__ void convert_x(const float* __restrict__ src)
{
    int i = (blockIdx.x * 256 + threadIdx.x) * 4;
    float4 v = *(const float4*)(src + i);
    float f[4] = {v.x, v.y, v.z, v.w};
    __half h[4], l[4];
    #pragma unroll
    for (int j = 0; j < 4; j++) {
        h[j] = __float2half_rn(f[j]);
        l[j] = __float2half_rn(f[j] - __half2float(h[j]));
    }
    *(uint2*)(g_Xhi + i) = *(uint2*)h;
    *(uint2*)(g_Xlo + i) = *(uint2*)l;
}
__global__ void convert_w4(const float* __restrict__ wq, const float* __restrict__ wk,
                           const float* __restrict__ wv, const float* __restrict__ wp)
{
    int y = blockIdx.y;
    const float* src = (y == 0) ? wq : (y == 1) ? wk : (y == 2) ? wv : wp;
    __half* dst = (y == 3) ? g_Ph : (g_Wh + (size_t)y * 1048576);
    int i = (blockIdx.x * 256 + threadIdx.x) * 4;
    float4 v = *(const float4*)(src + i);
    __half h[4] = {__float2half_rn(v.x), __float2half_rn(v.y),
                   __float2half_rn(v.z), __float2half_rn(v.w)};
    *(uint2*)(dst + i) = *(uint2*)h;
}

// ---------------------------------------------------------------------------
// GEMM: Y[4096 x N] = A[4096 x 1024] * B[N x 1024]^T, fp16 2-pass (A split).
// CTA tile 128x128, BK=32, 8 warps. 3-stage cp.async pipeline, ONE barrier
// per chunk, next-next load issued before compute. 2 CTAs/SM.
// ---------------------------------------------------------------------------
#define GS_STAGE 30720                 // 3 arrays * 128 rows * 80B
#define GS_DYN   92160                 // 3 stages (>= 67584 C-tile)

__global__ __launch_bounds__(256, 2) void gemm_mma(float* __restrict__ out, int mode)
{
    extern __shared__ __align__(16) char dyn[];
    __shared__ float invf[32];
    const uint32_t sb = smem_u32(dyn);
    const int tid = threadIdx.x, wid = tid >> 5, lane = tid & 31;
    const int wm = wid >> 2, wn = wid & 3;
    const int rBase = blockIdx.x * 128, nBase = blockIdx.y * 128;

    const __half *Ahi, *Alo, *Bh;
    if (mode == 0) { Ahi = g_Xhi; Alo = g_Xlo; Bh = g_Wh; }
    else           { Ahi = g_Ohi; Alo = g_Olo; Bh = g_Ph; }

    if (mode == 0 && tid < 32)
        invf[tid] = exp2f((float)(-2 * tid) * (0.015625f * 13.287712379549449f));

    auto load_chunk = [&](int c, int s) {
        const uint32_t base = sb + s * GS_STAGE;
        const int k0 = c * 32;
        #pragma unroll
        for (int i = 0; i < 2; i++) {
            int f = tid * 2 + i;            // 0..511
            int row = f >> 2, seg = f & 3;  // 4 x 16B per row
            uint32_t so = row * 80 + seg * 16;
            size_t ga = (size_t)(rBase + row) * 1024 + k0 + seg * 8;
            size_t gb = (size_t)(nBase + row) * 1024 + k0 + seg * 8;
            cp16(base + so,          Ahi + ga);
            cp16(base + 10240 + so,  Alo + ga);
            cp16(base + 20480 + so,  Bh  + gb);
        }
        CP_COMMIT();
    };

    float C[4][4][4];
    #pragma unroll
    for (int a = 0; a < 4; a++)
        #pragma unroll
        for (int b = 0; b < 4; b++)
            #pragma unroll
            for (int e = 0; e < 4; e++) C[a][b][e] = 0.f;

    load_chunk(0, 0);
    load_chunk(1, 1);

    int bufC = 0, bufN = 2;     // buffer of chunk c; buffer for chunk c+2
    for (int c = 0; c < 32; c++) {
        if (c < 31) { CP_WAIT1(); } else { CP_WAIT0(); }
        __syncthreads();        // chunk c visible to all; buf (c-1)%3 free
        if (c + 2 < 32) load_chunk(c + 2, bufN);
        const uint32_t base = sb + bufC * GS_STAGE;
        bufC = (bufC + 1 == 3) ? 0 : bufC + 1;
        bufN = (bufN + 1 == 3) ? 0 : bufN + 1;
        #pragma unroll
        for (int ks = 0; ks < 2; ks++) {
            uint32_t Ah[4][4], Al[4][4], Bf[4][2];
            const uint32_t acol = ks * 32 + (lane >> 4) * 16;
            #pragma unroll
            for (int mt = 0; mt < 4; mt++) {
                int row = wm * 64 + mt * 16 + (lane & 15);
                ldsm4(Ah[mt], base + row * 80 + acol);
                ldsm4(Al[mt], base + 10240 + row * 80 + acol);
            }
            const uint32_t bcol = ks * 32 + ((lane >> 3) & 1) * 16;
            #pragma unroll
            for (int ntp = 0; ntp < 2; ntp++) {
                int nrow = wn * 32 + ntp * 16 + ((lane >> 4) & 1) * 8 + (lane & 7);
                uint32_t r4[4];
                ldsm4(r4, base + 20480 + nrow * 80 + bcol);
                Bf[2 * ntp][0] = r4[0]; Bf[2 * ntp][1] = r4[1];
                Bf[2 * ntp + 1][0] = r4[2]; Bf[2 * ntp + 1][1] = r4[3];
            }
            #pragma unroll
            for (int mt = 0; mt < 4; mt++)
                #pragma unroll
                for (int nt = 0; nt < 4; nt++) {
                    mma_fp(C[mt][nt], Ah[mt], Bf[nt]);
                    mma_fp(C[mt][nt], Al[mt], Bf[nt]);
                }
        }
    }

    if (mode == 1) {
        #pragma unroll
        for (int mt = 0; mt < 4; mt++)
            #pragma unroll
            for (int nt = 0; nt < 4; nt++) {
                int r0 = rBase + wm * 64 + mt * 16 + (lane >> 2);
                int cc = nBase + wn * 32 + nt * 8 + 2 * (lane & 3);
                *(float2*)(out + (size_t)r0 * 1024 + cc) =
                    make_float2(C[mt][nt][0], C[mt][nt][1]);
                *(float2*)(out + (size_t)(r0 + 8) * 1024 + cc) =
                    make_float2(C[mt][nt][2], C[mt][nt][3]);
            }
        return;
    }

    // ---- mode 0: stage C tile through smem; stride 132 >= 128 cols ----
    float* Cs = (float*)dyn;   // [128][132] fp32 = 67584 B <= GS_DYN
    __syncthreads();           // all warps done reading pipeline buffers
    #pragma unroll
    for (int mt = 0; mt < 4; mt++)
        #pragma unroll
        for (int nt = 0; nt < 4; nt++) {
            int r0 = wm * 64 + mt * 16 + (lane >> 2);
            int cc = wn * 32 + nt * 8 + 2 * (lane & 3);
            *(float2*)&Cs[r0 * 132 + cc] = make_float2(C[mt][nt][0], C[mt][nt][1]);
            *(float2*)&Cs[(r0 + 8) * 132 + cc] = make_float2(C[mt][nt][2], C[mt][nt][3]);
        }
    __syncthreads();

    const int rowL = tid >> 1, headSel = tid & 1;
    const int r = rBase + rowL;
    const int b = r >> 11, t = r & (Tt - 1);
    const int gcol = nBase + headSel * 64;
    const int mat = gcol >> 10;
    const int head = (gcol & 1023) >> 6;

    float v[64];
    #pragma unroll
    for (int j = 0; j < 64; j++) v[j] = Cs[rowL * 132 + headSel * 64 + j];

    float o[64];
    if (mat == 2) {
        #pragma unroll
        for (int j = 0; j < 64; j++) o[j] = v[j];
    } else {
        float ss = 0.f;
        #pragma unroll
        for (int j = 0; j < 64; j++) ss += v[j] * v[j];
        float scl = rsqrtf(ss * (1.0f / 64.0f) + RMS_EPS);
        if (mat == 0) scl *= QSCALE;          // fold softmax scale + log2e into Q
        const float tf = (float)t;
        #pragma unroll
        for (int i = 0; i < 32; i++) {
            float x1 = v[i] * scl, x2 = v[i + 32] * scl;
            float sn, cn;
            sincosf(tf * invf[i], &sn, &cn);
            o[i] = fmaf(x1, cn, x2 * sn);
            o[i + 32] = fmaf(x2, cn, -x1 * sn);
        }
    }
    size_t doff = ((size_t)(b * Hh + head) * Tt + t) * Dd;
    if (mat == 0) {
        __half hb[64], lb[64];
        #pragma unroll
        for (int j = 0; j < 64; j++) {
            hb[j] = __float2half_rn(o[j]);
            lb[j] = __float2half_rn(o[j] - __half2float(hb[j]));
        }
        #pragma unroll
        for (int j = 0; j < 64; j += 8) {
            *(uint4*)(g_Qh + doff + j) = *(uint4*)(hb + j);
            *(uint4*)(g_Ql + doff + j) = *(uint4*)(lb + j);
        }
    } else {
        __half hb[64];
        #pragma unroll
        for (int j = 0; j < 64; j++) hb[j] = __float2half_rn(o[j]);
        __half* dh = (mat == 1) ? g_Kh : g_Vh;
        #pragma unroll
        for (int j = 0; j < 64; j += 8)
            *(uint4*)(dh + doff + j) = *(uint4*)(hb + j);
    }
}

// ---------------------------------------------------------------------------
// Flash attention via fp16 mma: 128 q rows/CTA, kv chunks of 64.
// 3-stage cp.async pipeline, ONE barrier per chunk, load ahead of compute.
// Scores arrive pre-scaled in log2 domain (QSCALE folded into Q).
// ---------------------------------------------------------------------------
#define AS_STAGE 18432
#define AS_TOTAL (3 * AS_STAGE)

__global__ __launch_bounds__(256, 2) void attn_mma()
{
    extern __shared__ __align__(16) char dyn[];
    const uint32_t sb = smem_u32(dyn);
    const int tid = threadIdx.x, wid = tid >> 5, lane = tid & 31;
    const int qt = 15 - (int)blockIdx.x;       // heavy tiles first
    const int bh = blockIdx.y;
    const int qBase = qt * 128;
    const size_t hoff = (size_t)bh * Tt * Dd;

    // ---- stage Q (128 x 64, hi/lo) across stage buffers 0/1 ----
    #pragma unroll
    for (int i = 0; i < 4; i++) {
        int f = tid * 4 + i;              // 0..1023
        int row = f >> 3, seg = f & 7;
        uint32_t so = row * 144 + seg * 16;
        size_t ga = hoff + (size_t)(qBase + row) * 64 + seg * 8;
        cp16(sb + so, g_Qh + ga);
        cp16(sb + 18432 + so, g_Ql + ga);
    }
    CP_COMMIT();
    CP_WAIT0();
    __syncthreads();

    uint32_t Qh[4][4], Ql[4][4];
    {
        int qrow = wid * 16 + (lane & 15);
        #pragma unroll
        for (int ks = 0; ks < 4; ks++) {
            uint32_t col = ks * 32 + (lane >> 4) * 16;
            ldsm4(Qh[ks], sb + qrow * 144 + col);
            ldsm4(Ql[ks], sb + 18432 + qrow * 144 + col);
        }
    }
    __syncthreads();

    auto load_chunk = [&](int kt, int s) {
        const uint32_t base = sb + s * AS_STAGE;
        const int kvb = kt * 64;
        #pragma unroll
        for (int i = 0; i < 2; i++) {
            int f = tid * 2 + i;          // 0..511
            int row = f >> 3, seg = f & 7;
            uint32_t so = row * 144 + seg * 16;
            size_t ga = hoff + (size_t)(kvb + row) * 64 + seg * 8;
            cp16(base + so,          g_Kh + ga);
            cp16(base + 9216 + so,   g_Vh + ga);
        }
        CP_COMMIT();
    };

    float O[8][4];
    #pragma unroll
    for (int nt = 0; nt < 8; nt++)
        #pragma unroll
        for (int e = 0; e < 4; e++) O[nt][e] = 0.f;
    float mr[2] = {-1e30f, -1e30f}, lr[2] = {0.f, 0.f};

    const int nChunks = 2 * qt + 2;
    load_chunk(0, 0);
    load_chunk(1, 1);

    const int r0 = qBase + wid * 16 + (lane >> 2);

    int bufC = 0, bufN = 2;
    for (int ct = 0; ct < nChunks; ct++) {
        if (ct + 1 < nChunks) { CP_WAIT1(); } else { CP_WAIT0(); }
        __syncthreads();        // chunk ct visible; buf (ct-1)%3 free
        if (ct + 2 < nChunks) load_chunk(ct + 2, bufN);
        const uint32_t base = sb + bufC * AS_STAGE;
        bufC = (bufC + 1 == 3) ? 0 : bufC + 1;
        bufN = (bufN + 1 == 3) ? 0 : bufN + 1;

        // ---- S = Q K^T (already scaled, log2 domain) ----
        float S[8][4];
        #pragma unroll
        for (int nt = 0; nt < 8; nt++)
            #pragma unroll
            for (int e = 0; e < 4; e++) S[nt][e] = 0.f;

        #pragma unroll
        for (int ks = 0; ks < 4; ks++) {
            const uint32_t bcol = ks * 32 + ((lane >> 3) & 1) * 16;
            #pragma unroll
            for (int ntp = 0; ntp < 4; ntp++) {
                int nrow = ntp * 16 + ((lane >> 4) & 1) * 8 + (lane & 7);
                uint32_t r4[4];
                ldsm4(r4, base + nrow * 144 + bcol);
                mma_fp(S[2 * ntp], Qh[ks], r4);
                mma_fp(S[2 * ntp], Ql[ks], r4);
                mma_fp(S[2 * ntp + 1], Qh[ks], r4 + 2);
                mma_fp(S[2 * ntp + 1], Ql[ks], r4 + 2);
            }
        }

        // ---- causal mask (last two chunks only) ----
        const int kvBase = ct * 64;
        if (ct >= 2 * qt) {
            #pragma unroll
            for (int nt = 0; nt < 8; nt++)
                #pragma unroll
                for (int e = 0; e < 4; e++) {
                    int row = r0 + (e >> 1) * 8;
                    int col = kvBase + nt * 8 + 2 * (lane & 3) + (e & 1);
                    if (col > row) S[nt][e] = -1e30f;
                }
        }

        // ---- online softmax (exp2 domain) ----
        #pragma unroll
        for (int half = 0; half < 2; half++) {
            float mx = -1e30f;
            #pragma unroll
            for (int nt = 0; nt < 8; nt++)
                mx = fmaxf(mx, fmaxf(S[nt][2 * half], S[nt][2 * half + 1]));
            mx = fmaxf(mx, __shfl_xor_sync(0xffffffffu, mx, 1));
            mx = fmaxf(mx, __shfl_xor_sync(0xffffffffu, mx, 2));
            float m_new = fmaxf(mr[half], mx);
            float corr = ex2(mr[half] - m_new);
            float rs = 0.f;
            #pragma unroll
            for (int nt = 0; nt < 8; nt++) {
                float p0 = ex2(S[nt][2 * half] - m_new);
                float p1 = ex2(S[nt][2 * half + 1] - m_new);
                S[nt][2 * half] = p0;
                S[nt][2 * half + 1] = p1;
                rs += p0 + p1;
            }
            rs += __shfl_xor_sync(0xffffffffu, rs, 1);
            rs += __shfl_xor_sync(0xffffffffu, rs, 2);
            lr[half] = lr[half] * corr + rs;
            mr[half] = m_new;
            #pragma unroll
            for (int nt = 0; nt < 8; nt++) {
                O[nt][2 * half] *= corr;
                O[nt][2 * half + 1] *= corr;
            }
        }

        // ---- O += P V, splitting P per k-slice (caps live registers) ----
        #pragma unroll
        for (int ks2 = 0; ks2 < 4; ks2++) {
            uint32_t Ph[4], Pl[4];
            {
                int t0 = 2 * ks2, t1 = t0 + 1;
                split2(S[t0][0], S[t0][1], Ph[0], Pl[0]);
                split2(S[t0][2], S[t0][3], Ph[1], Pl[1]);
                split2(S[t1][0], S[t1][1], Ph[2], Pl[2]);
                split2(S[t1][2], S[t1][3], Ph[3], Pl[3]);
            }
            int kvrow = ks2 * 16 + ((lane >> 3) & 1) * 8 + (lane & 7);
            #pragma unroll
            for (int ntp = 0; ntp < 4; ntp++) {
                uint32_t r4[4];
                uint32_t col = (2 * ntp + ((lane >> 4) & 1)) * 16;
                ldsm4t(r4, base + 9216 + kvrow * 144 + col);
                mma_fp(O[2 * ntp], Ph, r4);
                mma_fp(O[2 * ntp], Pl, r4);
                mma_fp(O[2 * ntp + 1], Ph, r4 + 2);
                mma_fp(O[2 * ntp + 1], Pl, r4 + 2);
            }
        }
    }

    // ---- epilogue: O /= l, write fp16 hi/lo to g_Ohi/g_Olo ----
    const int b = bh >> 4, head = bh & 15;
    #pragma unroll
    for (int half = 0; half < 2; half++) {
        float inv = 1.0f / lr[half];
        int t = qBase + wid * 16 + (lane >> 2) + 8 * half;
        size_t rbase = ((size_t)(b * Tt) + t) * 1024 + head * 64;
        #pragma unroll
        for (int nt = 0; nt < 8; nt++) {
            uint32_t h, l;
            split2(O[nt][2 * half] * inv, O[nt][2 * half + 1] * inv, h, l);
            size_t off = rbase + nt * 8 + 2 * (lane & 3);
            *(uint32_t*)(g_Ohi + off) = h;
            *(uint32_t*)(g_Olo + off) = l;
        }
    }
}

// ---------------------------------------------------------------------------
extern "C" void kernel_launch(void* const* d_in, const int* in_sizes, int n_in,
                              void* d_out, int out_size)
{
    (void)in_sizes; (void)n_in; (void)out_size;
    const float* x  = (const float*)d_in[0];
    const float* wq = (const float*)d_in[1];
    const float* wk = (const float*)d_in[2];
    const float* wv = (const float*)d_in[3];
    const float* wp = (const float*)d_in[4];
    float* out = (float*)d_out;

    convert_x<<<4096, 256>>>(x);
    convert_w4<<<dim3(1024, 4), 256>>>(wq, wk, wv, wp);

    cudaFuncSetAttribute(gemm_mma, cudaFuncAttributeMaxDynamicSharedMemorySize, GS_DYN);
    cudaFuncSetAttribute(attn_mma, cudaFuncAttributeMaxDynamicSharedMemorySize, AS_TOTAL);

    gemm_mma<<<dim3(32, 24), 256, GS_DYN>>>(nullptr, 0);     // QKV + norm + rope
    attn_mma<<<dim3(16, 32), 256, AS_TOTAL>>>();             // flash attention
    gemm_mma<<<dim3(32, 8), 256, GS_DYN>>>(out, 1);          // output projection
}

// round 13
// speedup vs baseline: 1.0968x; 1.0968x over previous
#include <cuda_runtime.h>
#include <cuda_fp16.h>
#include <math.h>
#include <stdint.h>

#define Bb 2
#define Tt 2048
#define Cc 1024
#define Hh 16
#define Dd 64
#define RMS_EPS 1.1920928955078125e-07f
// 0.125 * log2(e): folded into Q so QK^T scores are exp2-domain logits
#define QSCALE 0.1803368801111204f

// ---------------- scratch (allocation-free device globals) ----------------
__device__ __half g_Xhi[(size_t)4096*1024];
__device__ __half g_Xlo[(size_t)4096*1024];
__device__ __half g_Wh [(size_t)3072*1024];   // wq|wk|wv stacked rows, fp16
__device__ __half g_Ph [(size_t)1024*1024];   // w_proj fp16
__device__ __half g_Qh [(size_t)Bb*Hh*Tt*Dd];
__device__ __half g_Ql [(size_t)Bb*Hh*Tt*Dd];
__device__ __half g_Kh [(size_t)Bb*Hh*Tt*Dd];
__device__ __half g_Vh [(size_t)Bb*Hh*Tt*Dd];
__device__ __half g_Ohi[(size_t)4096*1024];   // attention out, [(b,t)][(h,d)]
__device__ __half g_Olo[(size_t)4096*1024];

// ---------------- helpers ----------------
__device__ __forceinline__ uint32_t smem_u32(const void* p) {
    uint32_t a;
    asm("{ .reg .u64 t; cvta.to.shared.u64 t, %1; cvt.u32.u64 %0, t; }" : "=r"(a) : "l"(p));
    return a;
}
__device__ __forceinline__ void cp16(uint32_t s, const void* g) {
    asm volatile("cp.async.cg.shared.global [%0], [%1], 16;" :: "r"(s), "l"(g));
}
#define CP_COMMIT() asm volatile("cp.async.commit_group;" ::: "memory")
#define CP_WAIT0()  asm volatile("cp.async.wait_group 0;" ::: "memory")
#define CP_WAIT1()  asm volatile("cp.async.wait_group 1;" ::: "memory")

__device__ __forceinline__ void ldsm4(uint32_t* r, uint32_t a) {
    asm volatile("ldmatrix.sync.aligned.m8n8.x4.shared.b16 {%0,%1,%2,%3}, [%4];"
                 : "=r"(r[0]), "=r"(r[1]), "=r"(r[2]), "=r"(r[3]) : "r"(a));
}
__device__ __forceinline__ void ldsm4t(uint32_t* r, uint32_t a) {
    asm volatile("ldmatrix.sync.aligned.m8n8.x4.trans.shared.b16 {%0,%1,%2,%3}, [%4];"
                 : "=r"(r[0]), "=r"(r[1]), "=r"(r[2]), "=r"(r[3]) : "r"(a));
}
__device__ __forceinline__ void mma_fp(float* d, const uint32_t* a, const uint32_t* b) {
    asm volatile(
        "mma.sync.aligned.m16n8k16.row.col.f32.f16.f16.f32 "
        "{%0,%1,%2,%3}, {%4,%5,%6,%7}, {%8,%9}, {%0,%1,%2,%3};"
        : "+f"(d[0]), "+f"(d[1]), "+f"(d[2]), "+f"(d[3])
        : "r"(a[0]), "r"(a[1]), "r"(a[2]), "r"(a[3]), "r"(b[0]), "r"(b[1]));
}
// raw ex2.approx (input already in log2 domain)
__device__ __forceinline__ float ex2(float x) {
    float r;
    asm("ex2.approx.f32 %0, %1;" : "=f"(r) : "f"(x));
    return r;
}
// split two fp32 into packed fp16x2 hi and lo words (elem a -> low half)
__device__ __forceinline__ void split2(float a, float b, uint32_t& h, uint32_t& l) {
    __half ah = __float2half_rn(a), bh = __float2half_rn(b);
    float al = a - __half2float(ah);
    float bl = b - __half2float(bh);
    __half hv[2] = {ah, bh};
    __half lv[2] = {__float2half_rn(al), __float2half_rn(bl)};
    h = *reinterpret_cast<uint32_t*>(hv);
    l = *reinterpret_cast<uint32_t*>(lv);
}

// ---------------- converts ----------------
__global__ void convert_x(const float* __restrict__ src)
{
    int i = (blockIdx.x * 256 + threadIdx.x) * 4;
    float4 v = *(const float4*)(src + i);
    float f[4] = {v.x, v.y, v.z, v.w};
    __half h[4], l[4];
    #pragma unroll
    for (int j = 0; j < 4; j++) {
        h[j] = __float2half_rn(f[j]);
        l[j] = __float2half_rn(f[j] - __half2float(h[j]));
    }
    *(uint2*)(g_Xhi + i) = *(uint2*)h;
    *(uint2*)(g_Xlo + i) = *(uint2*)l;
}
__global__ void convert_w4(const float* __restrict__ wq, const float* __restrict__ wk,
                           const float* __restrict__ wv, const float* __restrict__ wp)
{
    int y = blockIdx.y;
    const float* src = (y == 0) ? wq : (y == 1) ? wk : (y == 2) ? wv : wp;
    __half* dst = (y == 3) ? g_Ph : (g_Wh + (size_t)y * 1048576);
    int i = (blockIdx.x * 256 + threadIdx.x) * 4;
    float4 v = *(const float4*)(src + i);
    __half h[4] = {__float2half_rn(v.x), __float2half_rn(v.y),
                   __float2half_rn(v.z), __float2half_rn(v.w)};
    *(uint2*)(dst + i) = *(uint2*)h;
}

// ---------------------------------------------------------------------------
// GEMM: Y[4096 x N] = A[4096 x 1024] * B[N x 1024]^T, fp16 2-pass (A split).
// CTA tile 128x128, BK=32, 8 warps. 3-stage cp.async pipeline. 2 CTAs/SM.
// ---------------------------------------------------------------------------
#define GS_STAGE 30720                 // 3 arrays * 128 rows * 80B
#define GS_DYN   92160                 // 3 stages (>= 67584 C-tile)

__global__ __launch_bounds__(256, 2) void gemm_mma(float* __restrict__ out, int mode)
{
    extern __shared__ __align__(16) char dyn[];
    __shared__ float invf[32];
    const uint32_t sb = smem_u32(dyn);
    const int tid = threadIdx.x, wid = tid >> 5, lane = tid & 31;
    const int wm = wid >> 2, wn = wid & 3;
    const int rBase = blockIdx.x * 128, nBase = blockIdx.y * 128;

    const __half *Ahi, *Alo, *Bh;
    if (mode == 0) { Ahi = g_Xhi; Alo = g_Xlo; Bh = g_Wh; }
    else           { Ahi = g_Ohi; Alo = g_Olo; Bh = g_Ph; }

    if (mode == 0 && tid < 32)
        invf[tid] = exp2f((float)(-2 * tid) * (0.015625f * 13.287712379549449f));

    auto load_chunk = [&](int c, int s) {
        const uint32_t base = sb + s * GS_STAGE;
        const int k0 = c * 32;
        #pragma unroll
        for (int i = 0; i < 2; i++) {
            int f = tid * 2 + i;            // 0..511
            int row = f >> 2, seg = f & 3;  // 4 x 16B per row
            uint32_t so = row * 80 + seg * 16;
            size_t ga = (size_t)(rBase + row) * 1024 + k0 + seg * 8;
            size_t gb = (size_t)(nBase + row) * 1024 + k0 + seg * 8;
            cp16(base + so,          Ahi + ga);
            cp16(base + 10240 + so,  Alo + ga);
            cp16(base + 20480 + so,  Bh  + gb);
        }
        CP_COMMIT();
    };

    float C[4][4][4];
    #pragma unroll
    for (int a = 0; a < 4; a++)
        #pragma unroll
        for (int b = 0; b < 4; b++)
            #pragma unroll
            for (int e = 0; e < 4; e++) C[a][b][e] = 0.f;

    load_chunk(0, 0);
    load_chunk(1, 1);

    int bufC = 0, bufN = 2;     // buffer of chunk c; buffer for chunk c+2
    for (int c = 0; c < 32; c++) {
        if (c < 31) { CP_WAIT1(); } else { CP_WAIT0(); }
        __syncthreads();        // chunk c visible to all; buf (c-1)%3 free
        if (c + 2 < 32) load_chunk(c + 2, bufN);
        const uint32_t base = sb + bufC * GS_STAGE;
        bufC = (bufC + 1 == 3) ? 0 : bufC + 1;
        bufN = (bufN + 1 == 3) ? 0 : bufN + 1;
        #pragma unroll
        for (int ks = 0; ks < 2; ks++) {
            uint32_t Ah[4][4], Al[4][4], Bf[4][2];
            const uint32_t acol = ks * 32 + (lane >> 4) * 16;
            #pragma unroll
            for (int mt = 0; mt < 4; mt++) {
                int row = wm * 64 + mt * 16 + (lane & 15);
                ldsm4(Ah[mt], base + row * 80 + acol);
                ldsm4(Al[mt], base + 10240 + row * 80 + acol);
            }
            const uint32_t bcol = ks * 32 + ((lane >> 3) & 1) * 16;
            #pragma unroll
            for (int ntp = 0; ntp < 2; ntp++) {
                int nrow = wn * 32 + ntp * 16 + ((lane >> 4) & 1) * 8 + (lane & 7);
                uint32_t r4[4];
                ldsm4(r4, base + 20480 + nrow * 80 + bcol);
                Bf[2 * ntp][0] = r4[0]; Bf[2 * ntp][1] = r4[1];
                Bf[2 * ntp + 1][0] = r4[2]; Bf[2 * ntp + 1][1] = r4[3];
            }
            #pragma unroll
            for (int mt = 0; mt < 4; mt++)
                #pragma unroll
                for (int nt = 0; nt < 4; nt++) {
                    mma_fp(C[mt][nt], Ah[mt], Bf[nt]);
                    mma_fp(C[mt][nt], Al[mt], Bf[nt]);
                }
        }
    }

    if (mode == 1) {
        #pragma unroll
        for (int mt = 0; mt < 4; mt++)
            #pragma unroll
            for (int nt = 0; nt < 4; nt++) {
                int r0 = rBase + wm * 64 + mt * 16 + (lane >> 2);
                int cc = nBase + wn * 32 + nt * 8 + 2 * (lane & 3);
                *(float2*)(out + (size_t)r0 * 1024 + cc) =
                    make_float2(C[mt][nt][0], C[mt][nt][1]);
                *(float2*)(out + (size_t)(r0 + 8) * 1024 + cc) =
                    make_float2(C[mt][nt][2], C[mt][nt][3]);
            }
        return;
    }

    // ---- mode 0: stage C tile through smem; stride 132 >= 128 cols ----
    float* Cs = (float*)dyn;   // [128][132] fp32 = 67584 B <= GS_DYN
    __syncthreads();           // all warps done reading pipeline buffers
    #pragma unroll
    for (int mt = 0; mt < 4; mt++)
        #pragma unroll
        for (int nt = 0; nt < 4; nt++) {
            int r0 = wm * 64 + mt * 16 + (lane >> 2);
            int cc = wn * 32 + nt * 8 + 2 * (lane & 3);
            *(float2*)&Cs[r0 * 132 + cc] = make_float2(C[mt][nt][0], C[mt][nt][1]);
            *(float2*)&Cs[(r0 + 8) * 132 + cc] = make_float2(C[mt][nt][2], C[mt][nt][3]);
        }
    __syncthreads();

    const int rowL = tid >> 1, headSel = tid & 1;
    const int r = rBase + rowL;
    const int b = r >> 11, t = r & (Tt - 1);
    const int gcol = nBase + headSel * 64;
    const int mat = gcol >> 10;
    const int head = (gcol & 1023) >> 6;

    float v[64];
    #pragma unroll
    for (int j = 0; j < 64; j++) v[j] = Cs[rowL * 132 + headSel * 64 + j];

    float o[64];
    if (mat == 2) {
        #pragma unroll
        for (int j = 0; j < 64; j++) o[j] = v[j];
    } else {
        float ss = 0.f;
        #pragma unroll
        for (int j = 0; j < 64; j++) ss += v[j] * v[j];
        float scl = rsqrtf(ss * (1.0f / 64.0f) + RMS_EPS);
        if (mat == 0) scl *= QSCALE;          // fold softmax scale + log2e into Q
        const float tf = (float)t;
        #pragma unroll
        for (int i = 0; i < 32; i++) {
            float x1 = v[i] * scl, x2 = v[i + 32] * scl;
            float sn, cn;
            sincosf(tf * invf[i], &sn, &cn);
            o[i] = fmaf(x1, cn, x2 * sn);
            o[i + 32] = fmaf(x2, cn, -x1 * sn);
        }
    }
    size_t doff = ((size_t)(b * Hh + head) * Tt + t) * Dd;
    if (mat == 0) {
        __half hb[64], lb[64];
        #pragma unroll
        for (int j = 0; j < 64; j++) {
            hb[j] = __float2half_rn(o[j]);
            lb[j] = __float2half_rn(o[j] - __half2float(hb[j]));
        }
        #pragma unroll
        for (int j = 0; j < 64; j += 8) {
            *(uint4*)(g_Qh + doff + j) = *(uint4*)(hb + j);
            *(uint4*)(g_Ql + doff + j) = *(uint4*)(lb + j);
        }
    } else {
        __half hb[64];
        #pragma unroll
        for (int j = 0; j < 64; j++) hb[j] = __float2half_rn(o[j]);
        __half* dh = (mat == 1) ? g_Kh : g_Vh;
        #pragma unroll
        for (int j = 0; j < 64; j += 8)
            *(uint4*)(dh + doff + j) = *(uint4*)(hb + j);
    }
}

// ---------------------------------------------------------------------------
// Flash attention via fp16 mma: 128 q rows per tile, kv chunks of 64.
// LOAD-PAIRED: each CTA does q-tile (15-x) then (x) -> uniform 17 work units,
// grid 8x32 = 256 CTAs = one fully-resident balanced wave at 2 CTAs/SM.
// Scores arrive pre-scaled in log2 domain (QSCALE folded into Q).
// ---------------------------------------------------------------------------
#define AS_STAGE 18432
#define AS_TOTAL (3 * AS_STAGE)

__global__ __launch_bounds__(256, 2) void attn_mma()
{
    extern __shared__ __align__(16) char dyn[];
    const uint32_t sb = smem_u32(dyn);
    const int tid = threadIdx.x, wid = tid >> 5, lane = tid & 31;
    const int xIdx = (int)blockIdx.x;          // 0..7
    const int bh = blockIdx.y;
    const size_t hoff = (size_t)bh * Tt * Dd;
    const int b = bh >> 4, head = bh & 15;

    auto load_chunk = [&](int kt, int s) {
        const uint32_t base = sb + s * AS_STAGE;
        const int kvb = kt * 64;
        #pragma unroll
        for (int i = 0; i < 2; i++) {
            int f = tid * 2 + i;          // 0..511
            int row = f >> 3, seg = f & 7;
            uint32_t so = row * 144 + seg * 16;
            size_t ga = hoff + (size_t)(kvb + row) * 64 + seg * 8;
            cp16(base + so,          g_Kh + ga);
            cp16(base + 9216 + so,   g_Vh + ga);
        }
        CP_COMMIT();
    };

    for (int sub = 0; sub < 2; sub++) {
        const int qt = (sub == 0) ? (15 - xIdx) : xIdx;   // heavy first
        const int qBase = qt * 128;

        __syncthreads();   // prior sub-tile fully done with stage buffers

        // ---- stage Q (128 x 64, hi/lo) into stage buffers 0/1 ----
        #pragma unroll
        for (int i = 0; i < 4; i++) {
            int f = tid * 4 + i;              // 0..1023
            int row = f >> 3, seg = f & 7;
            uint32_t so = row * 144 + seg * 16;
            size_t ga = hoff + (size_t)(qBase + row) * 64 + seg * 8;
            cp16(sb + so, g_Qh + ga);
            cp16(sb + 18432 + so, g_Ql + ga);
        }
        CP_COMMIT();
        CP_WAIT0();
        __syncthreads();

        uint32_t Qh[4][4], Ql[4][4];
        {
            int qrow = wid * 16 + (lane & 15);
            #pragma unroll
            for (int ks = 0; ks < 4; ks++) {
                uint32_t col = ks * 32 + (lane >> 4) * 16;
                ldsm4(Qh[ks], sb + qrow * 144 + col);
                ldsm4(Ql[ks], sb + 18432 + qrow * 144 + col);
            }
        }
        __syncthreads();

        float O[8][4];
        #pragma unroll
        for (int nt = 0; nt < 8; nt++)
            #pragma unroll
            for (int e = 0; e < 4; e++) O[nt][e] = 0.f;
        float mr[2] = {-1e30f, -1e30f}, lr[2] = {0.f, 0.f};

        const int nChunks = 2 * qt + 2;
        load_chunk(0, 0);
        load_chunk(1, 1);

        const int r0 = qBase + wid * 16 + (lane >> 2);

        int bufC = 0, bufN = 2;
        for (int ct = 0; ct < nChunks; ct++) {
            if (ct + 1 < nChunks) { CP_WAIT1(); } else { CP_WAIT0(); }
            __syncthreads();        // chunk ct visible; buf (ct-1)%3 free
            if (ct + 2 < nChunks) load_chunk(ct + 2, bufN);
            const uint32_t base = sb + bufC * AS_STAGE;
            bufC = (bufC + 1 == 3) ? 0 : bufC + 1;
            bufN = (bufN + 1 == 3) ? 0 : bufN + 1;

            // ---- S = Q K^T (already scaled, log2 domain) ----
            float S[8][4];
            #pragma unroll
            for (int nt = 0; nt < 8; nt++)
                #pragma unroll
                for (int e = 0; e < 4; e++) S[nt][e] = 0.f;

            #pragma unroll
            for (int ks = 0; ks < 4; ks++) {
                const uint32_t bcol = ks * 32 + ((lane >> 3) & 1) * 16;
                #pragma unroll
                for (int ntp = 0; ntp < 4; ntp++) {
                    int nrow = ntp * 16 + ((lane >> 4) & 1) * 8 + (lane & 7);
                    uint32_t r4[4];
                    ldsm4(r4, base + nrow * 144 + bcol);
                    mma_fp(S[2 * ntp], Qh[ks], r4);
                    mma_fp(S[2 * ntp], Ql[ks], r4);
                    mma_fp(S[2 * ntp + 1], Qh[ks], r4 + 2);
                    mma_fp(S[2 * ntp + 1], Ql[ks], r4 + 2);
                }
            }

            // ---- causal mask (last two chunks only) ----
            const int kvBase = ct * 64;
            if (ct >= 2 * qt) {
                #pragma unroll
                for (int nt = 0; nt < 8; nt++)
                    #pragma unroll
                    for (int e = 0; e < 4; e++) {
                        int row = r0 + (e >> 1) * 8;
                        int col = kvBase + nt * 8 + 2 * (lane & 3) + (e & 1);
                        if (col > row) S[nt][e] = -1e30f;
                    }
            }

            // ---- online softmax (exp2 domain) ----
            #pragma unroll
            for (int half = 0; half < 2; half++) {
                float mx = -1e30f;
                #pragma unroll
                for (int nt = 0; nt < 8; nt++)
                    mx = fmaxf(mx, fmaxf(S[nt][2 * half], S[nt][2 * half + 1]));
                mx = fmaxf(mx, __shfl_xor_sync(0xffffffffu, mx, 1));
                mx = fmaxf(mx, __shfl_xor_sync(0xffffffffu, mx, 2));
                float m_new = fmaxf(mr[half], mx);
                float corr = ex2(mr[half] - m_new);
                float rs = 0.f;
                #pragma unroll
                for (int nt = 0; nt < 8; nt++) {
                    float p0 = ex2(S[nt][2 * half] - m_new);
                    float p1 = ex2(S[nt][2 * half + 1] - m_new);
                    S[nt][2 * half] = p0;
                    S[nt][2 * half + 1] = p1;
                    rs += p0 + p1;
                }
                rs += __shfl_xor_sync(0xffffffffu, rs, 1);
                rs += __shfl_xor_sync(0xffffffffu, rs, 2);
                lr[half] = lr[half] * corr + rs;
                mr[half] = m_new;
                #pragma unroll
                for (int nt = 0; nt < 8; nt++) {
                    O[nt][2 * half] *= corr;
                    O[nt][2 * half + 1] *= corr;
                }
            }

            // ---- O += P V, splitting P per k-slice (caps live registers) ----
            #pragma unroll
            for (int ks2 = 0; ks2 < 4; ks2++) {
                uint32_t Ph[4], Pl[4];
                {
                    int t0 = 2 * ks2, t1 = t0 + 1;
                    split2(S[t0][0], S[t0][1], Ph[0], Pl[0]);
                    split2(S[t0][2], S[t0][3], Ph[1], Pl[1]);
                    split2(S[t1][0], S[t1][1], Ph[2], Pl[2]);
                    split2(S[t1][2], S[t1][3], Ph[3], Pl[3]);
                }
                int kvrow = ks2 * 16 + ((lane >> 3) & 1) * 8 + (lane & 7);
                #pragma unroll
                for (int ntp = 0; ntp < 4; ntp++) {
                    uint32_t r4[4];
                    uint32_t col = (2 * ntp + ((lane >> 4) & 1)) * 16;
                    ldsm4t(r4, base + 9216 + kvrow * 144 + col);
                    mma_fp(O[2 * ntp], Ph, r4);
                    mma_fp(O[2 * ntp], Pl, r4);
                    mma_fp(O[2 * ntp + 1], Ph, r4 + 2);
                    mma_fp(O[2 * ntp + 1], Pl, r4 + 2);
                }
            }
        }

        // ---- epilogue: O /= l, write fp16 hi/lo to g_Ohi/g_Olo ----
        #pragma unroll
        for (int half = 0; half < 2; half++) {
            float inv = 1.0f / lr[half];
            int t = qBase + wid * 16 + (lane >> 2) + 8 * half;
            size_t rbase = ((size_t)(b * Tt) + t) * 1024 + head * 64;
            #pragma unroll
            for (int nt = 0; nt < 8; nt++) {
                uint32_t h, l;
                split2(O[nt][2 * half] * inv, O[nt][2 * half + 1] * inv, h, l);
                size_t off = rbase + nt * 8 + 2 * (lane & 3);
                *(uint32_t*)(g_Ohi + off) = h;
                *(uint32_t*)(g_Olo + off) = l;
            }
        }
    }
}

// ---------------------------------------------------------------------------
extern "C" void kernel_launch(void* const* d_in, const int* in_sizes, int n_in,
                              void* d_out, int out_size)
{
    (void)in_sizes; (void)n_in; (void)out_size;
    const float* x  = (const float*)d_in[0];
    const float* wq = (const float*)d_in[1];
    const float* wk = (const float*)d_in[2];
    const float* wv = (const float*)d_in[3];
    const float* wp = (const float*)d_in[4];
    float* out = (float*)d_out;

    convert_x<<<4096, 256>>>(x);
    convert_w4<<<dim3(1024, 4), 256>>>(wq, wk, wv, wp);

    cudaFuncSetAttribute(gemm_mma, cudaFuncAttributeMaxDynamicSharedMemorySize, GS_DYN);
    cudaFuncSetAttribute(attn_mma, cudaFuncAttributeMaxDynamicSharedMemorySize, AS_TOTAL);

    gemm_mma<<<dim3(32, 24), 256, GS_DYN>>>(nullptr, 0);     // QKV + norm + rope
    attn_mma<<<dim3(8, 32), 256, AS_TOTAL>>>();              // flash attention (paired)
    gemm_mma<<<dim3(32, 8), 256, GS_DYN>>>(out, 1);          // output projection
}

// round 14
// speedup vs baseline: 1.1671x; 1.0641x over previous
#include <cuda_runtime.h>
#include <cuda_fp16.h>
#include <math.h>
#include <stdint.h>

#define Bb 2
#define Tt 2048
#define Cc 1024
#define Hh 16
#define Dd 64
#define RMS_EPS 1.1920928955078125e-07f
// 0.125 * log2(e): folded into Q so QK^T scores are exp2-domain logits
#define QSCALE 0.1803368801111204f

// ---------------- scratch (allocation-free device globals) ----------------
__device__ __half g_Xh [(size_t)4096*1024];   // x fp16 (single precision pass)
__device__ __half g_Wh [(size_t)3072*1024];   // wq|wk|wv stacked rows, fp16
__device__ __half g_Ph [(size_t)1024*1024];   // w_proj fp16
__device__ __half g_Qh [(size_t)Bb*Hh*Tt*Dd];
__device__ __half g_Ql [(size_t)Bb*Hh*Tt*Dd];
__device__ __half g_Kh [(size_t)Bb*Hh*Tt*Dd];
__device__ __half g_Vh [(size_t)Bb*Hh*Tt*Dd];
__device__ __half g_Ohi[(size_t)4096*1024];   // attention out, [(b,t)][(h,d)]
__device__ __half g_Olo[(size_t)4096*1024];
__device__ float  g_rc [(size_t)Tt*32];       // rope cos table [t][i]
__device__ float  g_rs [(size_t)Tt*32];       // rope sin table [t][i]

// ---------------- helpers ----------------
__device__ __forceinline__ uint32_t smem_u32(const void* p) {
    uint32_t a;
    asm("{ .reg .u64 t; cvta.to.shared.u64 t, %1; cvt.u32.u64 %0, t; }" : "=r"(a) : "l"(p));
    return a;
}
__device__ __forceinline__ void cp16(uint32_t s, const void* g) {
    asm volatile("cp.async.cg.shared.global [%0], [%1], 16;" :: "r"(s), "l"(g));
}
#define CP_COMMIT() asm volatile("cp.async.commit_group;" ::: "memory")
#define CP_WAIT0()  asm volatile("cp.async.wait_group 0;" ::: "memory")
#define CP_WAIT1()  asm volatile("cp.async.wait_group 1;" ::: "memory")

__device__ __forceinline__ void ldsm4(uint32_t* r, uint32_t a) {
    asm volatile("ldmatrix.sync.aligned.m8n8.x4.shared.b16 {%0,%1,%2,%3}, [%4];"
                 : "=r"(r[0]), "=r"(r[1]), "=r"(r[2]), "=r"(r[3]) : "r"(a));
}
__device__ __forceinline__ void ldsm4t(uint32_t* r, uint32_t a) {
    asm volatile("ldmatrix.sync.aligned.m8n8.x4.trans.shared.b16 {%0,%1,%2,%3}, [%4];"
                 : "=r"(r[0]), "=r"(r[1]), "=r"(r[2]), "=r"(r[3]) : "r"(a));
}
__device__ __forceinline__ void mma_fp(float* d, const uint32_t* a, const uint32_t* b) {
    asm volatile(
        "mma.sync.aligned.m16n8k16.row.col.f32.f16.f16.f32 "
        "{%0,%1,%2,%3}, {%4,%5,%6,%7}, {%8,%9}, {%0,%1,%2,%3};"
        : "+f"(d[0]), "+f"(d[1]), "+f"(d[2]), "+f"(d[3])
        : "r"(a[0]), "r"(a[1]), "r"(a[2]), "r"(a[3]), "r"(b[0]), "r"(b[1]));
}
// raw ex2.approx (input already in log2 domain)
__device__ __forceinline__ float ex2(float x) {
    float r;
    asm("ex2.approx.f32 %0, %1;" : "=f"(r) : "f"(x));
    return r;
}
// split two fp32 into packed fp16x2 hi and lo words (elem a -> low half)
__device__ __forceinline__ void split2(float a, float b, uint32_t& h, uint32_t& l) {
    __half ah = __float2half_rn(a), bh = __float2half_rn(b);
    float al = a - __half2float(ah);
    float bl = b - __half2float(bh);
    __half hv[2] = {ah, bh};
    __half lv[2] = {__float2half_rn(al), __float2half_rn(bl)};
    h = *reinterpret_cast<uint32_t*>(hv);
    l = *reinterpret_cast<uint32_t*>(lv);
}

// ---------------- init / converts ----------------
__global__ void rope_init()
{
    int idx = blockIdx.x * 256 + threadIdx.x;    // 65536 total
    int t = idx >> 5, i = idx & 31;
    float invf = exp2f((float)(-2 * i) * (0.015625f * 13.287712379549449f));
    float sn, cn;
    sincosf((float)t * invf, &sn, &cn);
    g_rc[idx] = cn;
    g_rs[idx] = sn;
}
__global__ void convert_x(const float* __restrict__ src)
{
    int i = (blockIdx.x * 256 + threadIdx.x) * 4;
    float4 v = *(const float4*)(src + i);
    __half h[4] = {__float2half_rn(v.x), __float2half_rn(v.y),
                   __float2half_rn(v.z), __float2half_rn(v.w)};
    *(uint2*)(g_Xh + i) = *(uint2*)h;
}
__global__ void convert_w4(const float* __restrict__ wq, const float* __restrict__ wk,
                           const float* __restrict__ wv, const float* __restrict__ wp)
{
    int y = blockIdx.y;
    const float* src = (y == 0) ? wq : (y == 1) ? wk : (y == 2) ? wv : wp;
    __half* dst = (y == 3) ? g_Ph : (g_Wh + (size_t)y * 1048576);
    int i = (blockIdx.x * 256 + threadIdx.x) * 4;
    float4 v = *(const float4*)(src + i);
    __half h[4] = {__float2half_rn(v.x), __float2half_rn(v.y),
                   __float2half_rn(v.z), __float2half_rn(v.w)};
    *(uint2*)(dst + i) = *(uint2*)h;
}

// ---------------------------------------------------------------------------
// GEMM: Y[4096 x N] = A[4096 x 1024] * B[N x 1024]^T.
// mode 0: A = Xh SINGLE pass, B = Wh; epilogue RMSNorm+RoPE (table) -> QKV.
// mode 1: A = Ohi/Olo 2-pass, B = Ph; epilogue -> fp32 out.
// CTA tile 128x128, BK=32, 8 warps, 3-stage cp.async pipeline, 2 CTAs/SM.
// ---------------------------------------------------------------------------
#define GS_STAGE 30720                 // 3 arrays * 128 rows * 80B
#define GS_DYN   92160                 // 3 stages (>= 67584 C-tile)

__global__ __launch_bounds__(256, 2) void gemm_mma(float* __restrict__ out, int mode)
{
    extern __shared__ __align__(16) char dyn[];
    const uint32_t sb = smem_u32(dyn);
    const int tid = threadIdx.x, wid = tid >> 5, lane = tid & 31;
    const int wm = wid >> 2, wn = wid & 3;
    const int rBase = blockIdx.x * 128, nBase = blockIdx.y * 128;

    const __half *Ahi, *Alo, *Bh;
    if (mode == 0) { Ahi = g_Xh;  Alo = g_Xh;  Bh = g_Wh; }
    else           { Ahi = g_Ohi; Alo = g_Olo; Bh = g_Ph; }

    auto load_chunk = [&](int c, int s) {
        const uint32_t base = sb + s * GS_STAGE;
        const int k0 = c * 32;
        #pragma unroll
        for (int i = 0; i < 2; i++) {
            int f = tid * 2 + i;            // 0..511
            int row = f >> 2, seg = f & 3;  // 4 x 16B per row
            uint32_t so = row * 80 + seg * 16;
            size_t ga = (size_t)(rBase + row) * 1024 + k0 + seg * 8;
            size_t gb = (size_t)(nBase + row) * 1024 + k0 + seg * 8;
            cp16(base + so,          Ahi + ga);
            if (mode == 1) cp16(base + 10240 + so, Alo + ga);
            cp16(base + 20480 + so,  Bh  + gb);
        }
        CP_COMMIT();
    };

    float C[4][4][4];
    #pragma unroll
    for (int a = 0; a < 4; a++)
        #pragma unroll
        for (int b = 0; b < 4; b++)
            #pragma unroll
            for (int e = 0; e < 4; e++) C[a][b][e] = 0.f;

    load_chunk(0, 0);
    load_chunk(1, 1);

    int bufC = 0, bufN = 2;     // buffer of chunk c; buffer for chunk c+2
    for (int c = 0; c < 32; c++) {
        if (c < 31) { CP_WAIT1(); } else { CP_WAIT0(); }
        __syncthreads();        // chunk c visible to all; buf (c-1)%3 free
        if (c + 2 < 32) load_chunk(c + 2, bufN);
        const uint32_t base = sb + bufC * GS_STAGE;
        bufC = (bufC + 1 == 3) ? 0 : bufC + 1;
        bufN = (bufN + 1 == 3) ? 0 : bufN + 1;
        #pragma unroll
        for (int ks = 0; ks < 2; ks++) {
            uint32_t Ah[4][4], Al[4][4], Bf[4][2];
            const uint32_t acol = ks * 32 + (lane >> 4) * 16;
            #pragma unroll
            for (int mt = 0; mt < 4; mt++) {
                int row = wm * 64 + mt * 16 + (lane & 15);
                ldsm4(Ah[mt], base + row * 80 + acol);
                if (mode == 1) ldsm4(Al[mt], base + 10240 + row * 80 + acol);
            }
            const uint32_t bcol = ks * 32 + ((lane >> 3) & 1) * 16;
            #pragma unroll
            for (int ntp = 0; ntp < 2; ntp++) {
                int nrow = wn * 32 + ntp * 16 + ((lane >> 4) & 1) * 8 + (lane & 7);
                uint32_t r4[4];
                ldsm4(r4, base + 20480 + nrow * 80 + bcol);
                Bf[2 * ntp][0] = r4[0]; Bf[2 * ntp][1] = r4[1];
                Bf[2 * ntp + 1][0] = r4[2]; Bf[2 * ntp + 1][1] = r4[3];
            }
            #pragma unroll
            for (int mt = 0; mt < 4; mt++)
                #pragma unroll
                for (int nt = 0; nt < 4; nt++) {
                    mma_fp(C[mt][nt], Ah[mt], Bf[nt]);
                    if (mode == 1) mma_fp(C[mt][nt], Al[mt], Bf[nt]);
                }
        }
    }

    if (mode == 1) {
        #pragma unroll
        for (int mt = 0; mt < 4; mt++)
            #pragma unroll
            for (int nt = 0; nt < 4; nt++) {
                int r0 = rBase + wm * 64 + mt * 16 + (lane >> 2);
                int cc = nBase + wn * 32 + nt * 8 + 2 * (lane & 3);
                *(float2*)(out + (size_t)r0 * 1024 + cc) =
                    make_float2(C[mt][nt][0], C[mt][nt][1]);
                *(float2*)(out + (size_t)(r0 + 8) * 1024 + cc) =
                    make_float2(C[mt][nt][2], C[mt][nt][3]);
            }
        return;
    }

    // ---- mode 0: stage C tile through smem; stride 132 >= 128 cols ----
    float* Cs = (float*)dyn;   // [128][132] fp32 = 67584 B <= GS_DYN
    __syncthreads();           // all warps done reading pipeline buffers
    #pragma unroll
    for (int mt = 0; mt < 4; mt++)
        #pragma unroll
        for (int nt = 0; nt < 4; nt++) {
            int r0 = wm * 64 + mt * 16 + (lane >> 2);
            int cc = wn * 32 + nt * 8 + 2 * (lane & 3);
            *(float2*)&Cs[r0 * 132 + cc] = make_float2(C[mt][nt][0], C[mt][nt][1]);
            *(float2*)&Cs[(r0 + 8) * 132 + cc] = make_float2(C[mt][nt][2], C[mt][nt][3]);
        }
    __syncthreads();

    const int rowL = tid >> 1, headSel = tid & 1;
    const int r = rBase + rowL;
    const int b = r >> 11, t = r & (Tt - 1);
    const int gcol = nBase + headSel * 64;
    const int mat = gcol >> 10;
    const int head = (gcol & 1023) >> 6;

    float v[64];
    #pragma unroll
    for (int j = 0; j < 64; j++) v[j] = Cs[rowL * 132 + headSel * 64 + j];

    float o[64];
    if (mat == 2) {
        #pragma unroll
        for (int j = 0; j < 64; j++) o[j] = v[j];
    } else {
        float ss = 0.f;
        #pragma unroll
        for (int j = 0; j < 64; j++) ss += v[j] * v[j];
        float scl = rsqrtf(ss * (1.0f / 64.0f) + RMS_EPS);
        if (mat == 0) scl *= QSCALE;          // fold softmax scale + log2e into Q
        const float* rc = g_rc + (size_t)t * 32;
        const float* rs = g_rs + (size_t)t * 32;
        #pragma unroll
        for (int i = 0; i < 32; i += 4) {
            float4 c4 = *(const float4*)(rc + i);
            float4 s4 = *(const float4*)(rs + i);
            float cn[4] = {c4.x, c4.y, c4.z, c4.w};
            float sn[4] = {s4.x, s4.y, s4.z, s4.w};
            #pragma unroll
            for (int u = 0; u < 4; u++) {
                float x1 = v[i + u] * scl, x2 = v[i + u + 32] * scl;
                o[i + u] = fmaf(x1, cn[u], x2 * sn[u]);
                o[i + u + 32] = fmaf(x2, cn[u], -x1 * sn[u]);
            }
        }
    }
    size_t doff = ((size_t)(b * Hh + head) * Tt + t) * Dd;
    if (mat == 0) {
        __half hb[64], lb[64];
        #pragma unroll
        for (int j = 0; j < 64; j++) {
            hb[j] = __float2half_rn(o[j]);
            lb[j] = __float2half_rn(o[j] - __half2float(hb[j]));
        }
        #pragma unroll
        for (int j = 0; j < 64; j += 8) {
            *(uint4*)(g_Qh + doff + j) = *(uint4*)(hb + j);
            *(uint4*)(g_Ql + doff + j) = *(uint4*)(lb + j);
        }
    } else {
        __half hb[64];
        #pragma unroll
        for (int j = 0; j < 64; j++) hb[j] = __float2half_rn(o[j]);
        __half* dh = (mat == 1) ? g_Kh : g_Vh;
        #pragma unroll
        for (int j = 0; j < 64; j += 8)
            *(uint4*)(dh + doff + j) = *(uint4*)(hb + j);
    }
}

// ---------------------------------------------------------------------------
// Flash attention via fp16 mma: 128 q rows per tile, kv chunks of 64.
// LOAD-PAIRED: each CTA does q-tile (15-x) then (x) -> uniform 17 work units,
// grid 8x32 = 256 CTAs = one fully-resident balanced wave at 2 CTAs/SM.
// Scores arrive pre-scaled in log2 domain (QSCALE folded into Q).
// ---------------------------------------------------------------------------
#define AS_STAGE 18432
#define AS_TOTAL (3 * AS_STAGE)

__global__ __launch_bounds__(256, 2) void attn_mma()
{
    extern __shared__ __align__(16) char dyn[];
    const uint32_t sb = smem_u32(dyn);
    const int tid = threadIdx.x, wid = tid >> 5, lane = tid & 31;
    const int xIdx = (int)blockIdx.x;          // 0..7
    const int bh = blockIdx.y;
    const size_t hoff = (size_t)bh * Tt * Dd;
    const int b = bh >> 4, head = bh & 15;

    auto load_chunk = [&](int kt, int s) {
        const uint32_t base = sb + s * AS_STAGE;
        const int kvb = kt * 64;
        #pragma unroll
        for (int i = 0; i < 2; i++) {
            int f = tid * 2 + i;          // 0..511
            int row = f >> 3, seg = f & 7;
            uint32_t so = row * 144 + seg * 16;
            size_t ga = hoff + (size_t)(kvb + row) * 64 + seg * 8;
            cp16(base + so,          g_Kh + ga);
            cp16(base + 9216 + so,   g_Vh + ga);
        }
        CP_COMMIT();
    };

    for (int sub = 0; sub < 2; sub++) {
        const int qt = (sub == 0) ? (15 - xIdx) : xIdx;   // heavy first
        const int qBase = qt * 128;

        __syncthreads();   // prior sub-tile fully done with stage buffers

        // ---- stage Q (128 x 64, hi/lo) into stage buffers 0/1 ----
        #pragma unroll
        for (int i = 0; i < 4; i++) {
            int f = tid * 4 + i;              // 0..1023
            int row = f >> 3, seg = f & 7;
            uint32_t so = row * 144 + seg * 16;
            size_t ga = hoff + (size_t)(qBase + row) * 64 + seg * 8;
            cp16(sb + so, g_Qh + ga);
            cp16(sb + 18432 + so, g_Ql + ga);
        }
        CP_COMMIT();
        CP_WAIT0();
        __syncthreads();

        uint32_t Qh[4][4], Ql[4][4];
        {
            int qrow = wid * 16 + (lane & 15);
            #pragma unroll
            for (int ks = 0; ks < 4; ks++) {
                uint32_t col = ks * 32 + (lane >> 4) * 16;
                ldsm4(Qh[ks], sb + qrow * 144 + col);
                ldsm4(Ql[ks], sb + 18432 + qrow * 144 + col);
            }
        }
        __syncthreads();

        float O[8][4];
        #pragma unroll
        for (int nt = 0; nt < 8; nt++)
            #pragma unroll
            for (int e = 0; e < 4; e++) O[nt][e] = 0.f;
        float mr[2] = {-1e30f, -1e30f}, lr[2] = {0.f, 0.f};

        const int nChunks = 2 * qt + 2;
        load_chunk(0, 0);
        load_chunk(1, 1);

        const int r0 = qBase + wid * 16 + (lane >> 2);

        int bufC = 0, bufN = 2;
        for (int ct = 0; ct < nChunks; ct++) {
            if (ct + 1 < nChunks) { CP_WAIT1(); } else { CP_WAIT0(); }
            __syncthreads();        // chunk ct visible; buf (ct-1)%3 free
            if (ct + 2 < nChunks) load_chunk(ct + 2, bufN);
            const uint32_t base = sb + bufC * AS_STAGE;
            bufC = (bufC + 1 == 3) ? 0 : bufC + 1;
            bufN = (bufN + 1 == 3) ? 0 : bufN + 1;

            // ---- S = Q K^T (already scaled, log2 domain) ----
            float S[8][4];
            #pragma unroll
            for (int nt = 0; nt < 8; nt++)
                #pragma unroll
                for (int e = 0; e < 4; e++) S[nt][e] = 0.f;

            #pragma unroll
            for (int ks = 0; ks < 4; ks++) {
                const uint32_t bcol = ks * 32 + ((lane >> 3) & 1) * 16;
                #pragma unroll
                for (int ntp = 0; ntp < 4; ntp++) {
                    int nrow = ntp * 16 + ((lane >> 4) & 1) * 8 + (lane & 7);
                    uint32_t r4[4];
                    ldsm4(r4, base + nrow * 144 + bcol);
                    mma_fp(S[2 * ntp], Qh[ks], r4);
                    mma_fp(S[2 * ntp], Ql[ks], r4);
                    mma_fp(S[2 * ntp + 1], Qh[ks], r4 + 2);
                    mma_fp(S[2 * ntp + 1], Ql[ks], r4 + 2);
                }
            }

            // ---- causal mask (last two chunks only) ----
            const int kvBase = ct * 64;
            if (ct >= 2 * qt) {
                #pragma unroll
                for (int nt = 0; nt < 8; nt++)
                    #pragma unroll
                    for (int e = 0; e < 4; e++) {
                        int row = r0 + (e >> 1) * 8;
                        int col = kvBase + nt * 8 + 2 * (lane & 3) + (e & 1);
                        if (col > row) S[nt][e] = -1e30f;
                    }
            }

            // ---- online softmax (exp2 domain) ----
            #pragma unroll
            for (int half = 0; half < 2; half++) {
                float mx = -1e30f;
                #pragma unroll
                for (int nt = 0; nt < 8; nt++)
                    mx = fmaxf(mx, fmaxf(S[nt][2 * half], S[nt][2 * half + 1]));
                mx = fmaxf(mx, __shfl_xor_sync(0xffffffffu, mx, 1));
                mx = fmaxf(mx, __shfl_xor_sync(0xffffffffu, mx, 2));
                float m_new = fmaxf(mr[half], mx);
                float corr = ex2(mr[half] - m_new);
                float rs = 0.f;
                #pragma unroll
                for (int nt = 0; nt < 8; nt++) {
                    float p0 = ex2(S[nt][2 * half] - m_new);
                    float p1 = ex2(S[nt][2 * half + 1] - m_new);
                    S[nt][2 * half] = p0;
                    S[nt][2 * half + 1] = p1;
                    rs += p0 + p1;
                }
                rs += __shfl_xor_sync(0xffffffffu, rs, 1);
                rs += __shfl_xor_sync(0xffffffffu, rs, 2);
                lr[half] = lr[half] * corr + rs;
                mr[half] = m_new;
                #pragma unroll
                for (int nt = 0; nt < 8; nt++) {
                    O[nt][2 * half] *= corr;
                    O[nt][2 * half + 1] *= corr;
                }
            }

            // ---- O += P V, splitting P per k-slice (caps live registers) ----
            #pragma unroll
            for (int ks2 = 0; ks2 < 4; ks2++) {
                uint32_t Ph[4], Pl[4];
                {
                    int t0 = 2 * ks2, t1 = t0 + 1;
                    split2(S[t0][0], S[t0][1], Ph[0], Pl[0]);
                    split2(S[t0][2], S[t0][3], Ph[1], Pl[1]);
                    split2(S[t1][0], S[t1][1], Ph[2], Pl[2]);
                    split2(S[t1][2], S[t1][3], Ph[3], Pl[3]);
                }
                int kvrow = ks2 * 16 + ((lane >> 3) & 1) * 8 + (lane & 7);
                #pragma unroll
                for (int ntp = 0; ntp < 4; ntp++) {
                    uint32_t r4[4];
                    uint32_t col = (2 * ntp + ((lane >> 4) & 1)) * 16;
                    ldsm4t(r4, base + 9216 + kvrow * 144 + col);
                    mma_fp(O[2 * ntp], Ph, r4);
                    mma_fp(O[2 * ntp], Pl, r4);
                    mma_fp(O[2 * ntp + 1], Ph, r4 + 2);
                    mma_fp(O[2 * ntp + 1], Pl, r4 + 2);
                }
            }
        }

        // ---- epilogue: O /= l, write fp16 hi/lo to g_Ohi/g_Olo ----
        #pragma unroll
        for (int half = 0; half < 2; half++) {
            float inv = 1.0f / lr[half];
            int t = qBase + wid * 16 + (lane >> 2) + 8 * half;
            size_t rbase = ((size_t)(b * Tt) + t) * 1024 + head * 64;
            #pragma unroll
            for (int nt = 0; nt < 8; nt++) {
                uint32_t h, l;
                split2(O[nt][2 * half] * inv, O[nt][2 * half + 1] * inv, h, l);
                size_t off = rbase + nt * 8 + 2 * (lane & 3);
                *(uint32_t*)(g_Ohi + off) = h;
                *(uint32_t*)(g_Olo + off) = l;
            }
        }
    }
}

// ---------------------------------------------------------------------------
extern "C" void kernel_launch(void* const* d_in, const int* in_sizes, int n_in,
                              void* d_out, int out_size)
{
    (void)in_sizes; (void)n_in; (void)out_size;
    const float* x  = (const float*)d_in[0];
    const float* wq = (const float*)d_in[1];
    const float* wk = (const float*)d_in[2];
    const float* wv = (const float*)d_in[3];
    const float* wp = (const float*)d_in[4];
    float* out = (float*)d_out;

    rope_init<<<256, 256>>>();
    convert_x<<<4096, 256>>>(x);
    convert_w4<<<dim3(1024, 4), 256>>>(wq, wk, wv, wp);

    cudaFuncSetAttribute(gemm_mma, cudaFuncAttributeMaxDynamicSharedMemorySize, GS_DYN);
    cudaFuncSetAttribute(attn_mma, cudaFuncAttributeMaxDynamicSharedMemorySize, AS_TOTAL);

    gemm_mma<<<dim3(32, 24), 256, GS_DYN>>>(nullptr, 0);     // QKV + norm + rope
    attn_mma<<<dim3(8, 32), 256, AS_TOTAL>>>();              // flash attention (paired)
    gemm_mma<<<dim3(32, 8), 256, GS_DYN>>>(out, 1);          // output projection
}

// round 15
// speedup vs baseline: 1.4087x; 1.2070x over previous
#include <cuda_runtime.h>
#include <cuda_fp16.h>
#include <math.h>
#include <stdint.h>

#define Bb 2
#define Tt 2048
#define Cc 1024
#define Hh 16
#define Dd 64
#define RMS_EPS 1.1920928955078125e-07f
// 0.125 * log2(e): folded into Q so QK^T scores are exp2-domain logits
#define QSCALE 0.1803368801111204f

// ---------------- scratch (allocation-free device globals) ----------------
__device__ __half g_Xh [(size_t)4096*1024];   // x fp16
__device__ __half g_Wh [(size_t)3072*1024];   // wq|wk|wv stacked rows, fp16
__device__ __half g_Ph [(size_t)1024*1024];   // w_proj fp16
__device__ __half g_Qh [(size_t)Bb*Hh*Tt*Dd];
__device__ __half g_Ql [(size_t)Bb*Hh*Tt*Dd];
__device__ __half g_Kh [(size_t)Bb*Hh*Tt*Dd];
__device__ __half g_Vh [(size_t)Bb*Hh*Tt*Dd];
__device__ __half g_Oh [(size_t)4096*1024];   // attention out, [(b,t)][(h,d)]
__device__ float  g_rc [(size_t)Tt*32];       // rope cos table [t][i]
__device__ float  g_rs [(size_t)Tt*32];       // rope sin table [t][i]

// ---------------- helpers ----------------
__device__ __forceinline__ uint32_t smem_u32(const void* p) {
    uint32_t a;
    asm("{ .reg .u64 t; cvta.to.shared.u64 t, %1; cvt.u32.u64 %0, t; }" : "=r"(a) : "l"(p));
    return a;
}
__device__ __forceinline__ void cp16(uint32_t s, const void* g) {
    asm volatile("cp.async.cg.shared.global [%0], [%1], 16;" :: "r"(s), "l"(g));
}
#define CP_COMMIT() asm volatile("cp.async.commit_group;" ::: "memory")
#define CP_WAIT0()  asm volatile("cp.async.wait_group 0;" ::: "memory")
#define CP_WAIT1()  asm volatile("cp.async.wait_group 1;" ::: "memory")

__device__ __forceinline__ void ldsm4(uint32_t* r, uint32_t a) {
    asm volatile("ldmatrix.sync.aligned.m8n8.x4.shared.b16 {%0,%1,%2,%3}, [%4];"
                 : "=r"(r[0]), "=r"(r[1]), "=r"(r[2]), "=r"(r[3]) : "r"(a));
}
__device__ __forceinline__ void ldsm4t(uint32_t* r, uint32_t a) {
    asm volatile("ldmatrix.sync.aligned.m8n8.x4.trans.shared.b16 {%0,%1,%2,%3}, [%4];"
                 : "=r"(r[0]), "=r"(r[1]), "=r"(r[2]), "=r"(r[3]) : "r"(a));
}
__device__ __forceinline__ void mma_fp(float* d, const uint32_t* a, const uint32_t* b) {
    asm volatile(
        "mma.sync.aligned.m16n8k16.row.col.f32.f16.f16.f32 "
        "{%0,%1,%2,%3}, {%4,%5,%6,%7}, {%8,%9}, {%0,%1,%2,%3};"
        : "+f"(d[0]), "+f"(d[1]), "+f"(d[2]), "+f"(d[3])
        : "r"(a[0]), "r"(a[1]), "r"(a[2]), "r"(a[3]), "r"(b[0]), "r"(b[1]));
}
// raw ex2.approx (input already in log2 domain)
__device__ __forceinline__ float ex2(float x) {
    float r;
    asm("ex2.approx.f32 %0, %1;" : "=f"(r) : "f"(x));
    return r;
}
// split two fp32 into packed fp16x2 hi and lo words (elem a -> low half)
__device__ __forceinline__ void split2(float a, float b, uint32_t& h, uint32_t& l) {
    __half ah = __float2half_rn(a), bh = __float2half_rn(b);
    float al = a - __half2float(ah);
    float bl = b - __half2float(bh);
    __half hv[2] = {ah, bh};
    __half lv[2] = {__float2half_rn(al), __float2half_rn(bl)};
    h = *reinterpret_cast<uint32_t*>(hv);
    l = *reinterpret_cast<uint32_t*>(lv);
}
__device__ __forceinline__ uint32_t pack2h(float a, float b) {
    __half hv[2] = {__float2half_rn(a), __float2half_rn(b)};
    return *reinterpret_cast<uint32_t*>(hv);
}

// ---------------- init / converts ----------------
__global__ void rope_init()
{
    int idx = blockIdx.x * 256 + threadIdx.x;    // 65536 total
    int t = idx >> 5, i = idx & 31;
    float invf = exp2f((float)(-2 * i) * (0.015625f * 13.287712379549449f));
    float sn, cn;
    sincosf((float)t * invf, &sn, &cn);
    g_rc[idx] = cn;
    g_rs[idx] = sn;
}
__global__ void convert_x(const float* __restrict__ src)
{
    int i = (blockIdx.x * 256 + threadIdx.x) * 4;
    float4 v = *(const float4*)(src + i);
    __half h[4] = {__float2half_rn(v.x), __float2half_rn(v.y),
                   __float2half_rn(v.z), __float2half_rn(v.w)};
    *(uint2*)(g_Xh + i) = *(uint2*)h;
}
__global__ void convert_w4(const float* __restrict__ wq, const float* __restrict__ wk,
                           const float* __restrict__ wv, const float* __restrict__ wp)
{
    int y = blockIdx.y;
    const float* src = (y == 0) ? wq : (y == 1) ? wk : (y == 2) ? wv : wp;
    __half* dst = (y == 3) ? g_Ph : (g_Wh + (size_t)y * 1048576);
    int i = (blockIdx.x * 256 + threadIdx.x) * 4;
    float4 v = *(const float4*)(src + i);
    __half h[4] = {__float2half_rn(v.x), __float2half_rn(v.y),
                   __float2half_rn(v.z), __float2half_rn(v.w)};
    *(uint2*)(dst + i) = *(uint2*)h;
}

// ---------------------------------------------------------------------------
// GEMM: Y[4096 x N] = A[4096 x 1024] * B[N x 1024]^T, single-pass fp16 A.
// CTA tile 128x128, BK=64, 8 warps, 3-stage cp.async pipeline, 2 CTAs/SM.
// mode 0: A = Xh, B = Wh; epilogue RMSNorm + RoPE table -> Q(hi/lo), K, V.
// mode 1: A = Oh, B = Ph; epilogue -> fp32 out.
// ---------------------------------------------------------------------------
#define GS_STAGE 36864                 // (A 128 + B 128 rows) x 144B
#define GS_DYN   110592                // 3 stages (>= 67584 C-tile)

__global__ __launch_bounds__(256, 2) void gemm_mma(float* __restrict__ out, int mode)
{
    extern __shared__ __align__(16) char dyn[];
    const uint32_t sb = smem_u32(dyn);
    const int tid = threadIdx.x, wid = tid >> 5, lane = tid & 31;
    const int wm = wid >> 2, wn = wid & 3;
    const int rBase = blockIdx.x * 128, nBase = blockIdx.y * 128;

    const __half* A = (mode == 0) ? g_Xh : g_Oh;
    const __half* Bh = (mode == 0) ? g_Wh : g_Ph;

    auto load_chunk = [&](int c, int s) {
        const uint32_t base = sb + s * GS_STAGE;
        const int k0 = c * 64;
        #pragma unroll
        for (int i = 0; i < 4; i++) {
            int f = tid * 4 + i;            // 0..1023
            int row = f >> 3, seg = f & 7;  // 8 x 16B per row
            uint32_t so = row * 144 + seg * 16;
            cp16(base + so,         A  + (size_t)(rBase + row) * 1024 + k0 + seg * 8);
            cp16(base + 18432 + so, Bh + (size_t)(nBase + row) * 1024 + k0 + seg * 8);
        }
        CP_COMMIT();
    };

    float C[4][4][4];
    #pragma unroll
    for (int a = 0; a < 4; a++)
        #pragma unroll
        for (int b = 0; b < 4; b++)
            #pragma unroll
            for (int e = 0; e < 4; e++) C[a][b][e] = 0.f;

    load_chunk(0, 0);
    load_chunk(1, 1);

    int bufC = 0, bufN = 2;     // buffer of chunk c; buffer for chunk c+2
    for (int c = 0; c < 16; c++) {
        if (c < 15) { CP_WAIT1(); } else { CP_WAIT0(); }
        __syncthreads();        // chunk c visible; buf (c-1)%3 free
        if (c + 2 < 16) load_chunk(c + 2, bufN);
        const uint32_t base = sb + bufC * GS_STAGE;
        bufC = (bufC + 1 == 3) ? 0 : bufC + 1;
        bufN = (bufN + 1 == 3) ? 0 : bufN + 1;
        #pragma unroll
        for (int ks = 0; ks < 4; ks++) {
            uint32_t Af[4][4], Bf[4][2];
            const uint32_t acol = ks * 32 + (lane >> 4) * 16;
            #pragma unroll
            for (int mt = 0; mt < 4; mt++) {
                int row = wm * 64 + mt * 16 + (lane & 15);
                ldsm4(Af[mt], base + row * 144 + acol);
            }
            const uint32_t bcol = ks * 32 + ((lane >> 3) & 1) * 16;
            #pragma unroll
            for (int ntp = 0; ntp < 2; ntp++) {
                int nrow = wn * 32 + ntp * 16 + ((lane >> 4) & 1) * 8 + (lane & 7);
                uint32_t r4[4];
                ldsm4(r4, base + 18432 + nrow * 144 + bcol);
                Bf[2 * ntp][0] = r4[0]; Bf[2 * ntp][1] = r4[1];
                Bf[2 * ntp + 1][0] = r4[2]; Bf[2 * ntp + 1][1] = r4[3];
            }
            #pragma unroll
            for (int mt = 0; mt < 4; mt++)
                #pragma unroll
                for (int nt = 0; nt < 4; nt++)
                    mma_fp(C[mt][nt], Af[mt], Bf[nt]);
        }
    }

    if (mode == 1) {
        #pragma unroll
        for (int mt = 0; mt < 4; mt++)
            #pragma unroll
            for (int nt = 0; nt < 4; nt++) {
                int r0 = rBase + wm * 64 + mt * 16 + (lane >> 2);
                int cc = nBase + wn * 32 + nt * 8 + 2 * (lane & 3);
                *(float2*)(out + (size_t)r0 * 1024 + cc) =
                    make_float2(C[mt][nt][0], C[mt][nt][1]);
                *(float2*)(out + (size_t)(r0 + 8) * 1024 + cc) =
                    make_float2(C[mt][nt][2], C[mt][nt][3]);
            }
        return;
    }

    // ---- mode 0: stage C tile through smem; stride 132 >= 128 cols ----
    float* Cs = (float*)dyn;   // [128][132] fp32 = 67584 B <= GS_DYN
    __syncthreads();           // all warps done reading pipeline buffers
    #pragma unroll
    for (int mt = 0; mt < 4; mt++)
        #pragma unroll
        for (int nt = 0; nt < 4; nt++) {
            int r0 = wm * 64 + mt * 16 + (lane >> 2);
            int cc = wn * 32 + nt * 8 + 2 * (lane & 3);
            *(float2*)&Cs[r0 * 132 + cc] = make_float2(C[mt][nt][0], C[mt][nt][1]);
            *(float2*)&Cs[(r0 + 8) * 132 + cc] = make_float2(C[mt][nt][2], C[mt][nt][3]);
        }
    __syncthreads();

    const int rowL = tid >> 1, headSel = tid & 1;
    const int r = rBase + rowL;
    const int b = r >> 11, t = r & (Tt - 1);
    const int gcol = nBase + headSel * 64;
    const int mat = gcol >> 10;
    const int head = (gcol & 1023) >> 6;

    float v[64];
    #pragma unroll
    for (int j = 0; j < 64; j++) v[j] = Cs[rowL * 132 + headSel * 64 + j];

    float o[64];
    if (mat == 2) {
        #pragma unroll
        for (int j = 0; j < 64; j++) o[j] = v[j];
    } else {
        float ss = 0.f;
        #pragma unroll
        for (int j = 0; j < 64; j++) ss += v[j] * v[j];
        float scl = rsqrtf(ss * (1.0f / 64.0f) + RMS_EPS);
        if (mat == 0) scl *= QSCALE;          // fold softmax scale + log2e into Q
        const float* rc = g_rc + (size_t)t * 32;
        const float* rs = g_rs + (size_t)t * 32;
        #pragma unroll
        for (int i = 0; i < 32; i += 4) {
            float4 c4 = *(const float4*)(rc + i);
            float4 s4 = *(const float4*)(rs + i);
            float cn[4] = {c4.x, c4.y, c4.z, c4.w};
            float sn[4] = {s4.x, s4.y, s4.z, s4.w};
            #pragma unroll
            for (int u = 0; u < 4; u++) {
                float x1 = v[i + u] * scl, x2 = v[i + u + 32] * scl;
                o[i + u] = fmaf(x1, cn[u], x2 * sn[u]);
                o[i + u + 32] = fmaf(x2, cn[u], -x1 * sn[u]);
            }
        }
    }
    size_t doff = ((size_t)(b * Hh + head) * Tt + t) * Dd;
    if (mat == 0) {
        __half hb[64], lb[64];
        #pragma unroll
        for (int j = 0; j < 64; j++) {
            hb[j] = __float2half_rn(o[j]);
            lb[j] = __float2half_rn(o[j] - __half2float(hb[j]));
        }
        #pragma unroll
        for (int j = 0; j < 64; j += 8) {
            *(uint4*)(g_Qh + doff + j) = *(uint4*)(hb + j);
            *(uint4*)(g_Ql + doff + j) = *(uint4*)(lb + j);
        }
    } else {
        __half hb[64];
        #pragma unroll
        for (int j = 0; j < 64; j++) hb[j] = __float2half_rn(o[j]);
        __half* dh = (mat == 1) ? g_Kh : g_Vh;
        #pragma unroll
        for (int j = 0; j < 64; j += 8)
            *(uint4*)(dh + doff + j) = *(uint4*)(hb + j);
    }
}

// ---------------------------------------------------------------------------
// Flash attention via fp16 mma: 128 q rows per tile, kv chunks of 64.
// LOAD-PAIRED: each CTA does q-tile (15-x) then (x) -> uniform 17 work units,
// grid 8x32 = 256 CTAs = one fully-resident balanced wave at 2 CTAs/SM.
// Scores arrive pre-scaled in log2 domain (QSCALE folded into Q).
// ---------------------------------------------------------------------------
#define AS_STAGE 18432
#define AS_TOTAL (3 * AS_STAGE)

__global__ __launch_bounds__(256, 2) void attn_mma()
{
    extern __shared__ __align__(16) char dyn[];
    const uint32_t sb = smem_u32(dyn);
    const int tid = threadIdx.x, wid = tid >> 5, lane = tid & 31;
    const int xIdx = (int)blockIdx.x;          // 0..7
    const int bh = blockIdx.y;
    const size_t hoff = (size_t)bh * Tt * Dd;
    const int b = bh >> 4, head = bh & 15;

    auto load_chunk = [&](int kt, int s) {
        const uint32_t base = sb + s * AS_STAGE;
        const int kvb = kt * 64;
        #pragma unroll
        for (int i = 0; i < 2; i++) {
            int f = tid * 2 + i;          // 0..511
            int row = f >> 3, seg = f & 7;
            uint32_t so = row * 144 + seg * 16;
            size_t ga = hoff + (size_t)(kvb + row) * 64 + seg * 8;
            cp16(base + so,          g_Kh + ga);
            cp16(base + 9216 + so,   g_Vh + ga);
        }
        CP_COMMIT();
    };

    for (int sub = 0; sub < 2; sub++) {
        const int qt = (sub == 0) ? (15 - xIdx) : xIdx;   // heavy first
        const int qBase = qt * 128;

        __syncthreads();   // prior sub-tile fully done with stage buffers

        // ---- stage Q (128 x 64, hi/lo) into stage buffers 0/1 ----
        #pragma unroll
        for (int i = 0; i < 4; i++) {
            int f = tid * 4 + i;              // 0..1023
            int row = f >> 3, seg = f & 7;
            uint32_t so = row * 144 + seg * 16;
            size_t ga = hoff + (size_t)(qBase + row) * 64 + seg * 8;
            cp16(sb + so, g_Qh + ga);
            cp16(sb + 18432 + so, g_Ql + ga);
        }
        CP_COMMIT();
        CP_WAIT0();
        __syncthreads();

        uint32_t Qh[4][4], Ql[4][4];
        {
            int qrow = wid * 16 + (lane & 15);
            #pragma unroll
            for (int ks = 0; ks < 4; ks++) {
                uint32_t col = ks * 32 + (lane >> 4) * 16;
                ldsm4(Qh[ks], sb + qrow * 144 + col);
                ldsm4(Ql[ks], sb + 18432 + qrow * 144 + col);
            }
        }
        __syncthreads();

        float O[8][4];
        #pragma unroll
        for (int nt = 0; nt < 8; nt++)
            #pragma unroll
            for (int e = 0; e < 4; e++) O[nt][e] = 0.f;
        float mr[2] = {-1e30f, -1e30f}, lr[2] = {0.f, 0.f};

        const int nChunks = 2 * qt + 2;
        load_chunk(0, 0);
        load_chunk(1, 1);

        const int r0 = qBase + wid * 16 + (lane >> 2);

        int bufC = 0, bufN = 2;
        for (int ct = 0; ct < nChunks; ct++) {
            if (ct + 1 < nChunks) { CP_WAIT1(); } else { CP_WAIT0(); }
            __syncthreads();        // chunk ct visible; buf (ct-1)%3 free
            if (ct + 2 < nChunks) load_chunk(ct + 2, bufN);
            const uint32_t base = sb + bufC * AS_STAGE;
            bufC = (bufC + 1 == 3) ? 0 : bufC + 1;
            bufN = (bufN + 1 == 3) ? 0 : bufN + 1;

            // ---- S = Q K^T (already scaled, log2 domain) ----
            float S[8][4];
            #pragma unroll
            for (int nt = 0; nt < 8; nt++)
                #pragma unroll
                for (int e = 0; e < 4; e++) S[nt][e] = 0.f;

            #pragma unroll
            for (int ks = 0; ks < 4; ks++) {
                const uint32_t bcol = ks * 32 + ((lane >> 3) & 1) * 16;
                #pragma unroll
                for (int ntp = 0; ntp < 4; ntp++) {
                    int nrow = ntp * 16 + ((lane >> 4) & 1) * 8 + (lane & 7);
                    uint32_t r4[4];
                    ldsm4(r4, base + nrow * 144 + bcol);
                    mma_fp(S[2 * ntp], Qh[ks], r4);
                    mma_fp(S[2 * ntp], Ql[ks], r4);
                    mma_fp(S[2 * ntp + 1], Qh[ks], r4 + 2);
                    mma_fp(S[2 * ntp + 1], Ql[ks], r4 + 2);
                }
            }

            // ---- causal mask (last two chunks only) ----
            const int kvBase = ct * 64;
            if (ct >= 2 * qt) {
                #pragma unroll
                for (int nt = 0; nt < 8; nt++)
                    #pragma unroll
                    for (int e = 0; e < 4; e++) {
                        int row = r0 + (e >> 1) * 8;
                        int col = kvBase + nt * 8 + 2 * (lane & 3) + (e & 1);
                        if (col > row) S[nt][e] = -1e30f;
                    }
            }

            // ---- online softmax (exp2 domain) ----
            #pragma unroll
            for (int half = 0; half < 2; half++) {
                float mx = -1e30f;
                #pragma unroll
                for (int nt = 0; nt < 8; nt++)
                    mx = fmaxf(mx, fmaxf(S[nt][2 * half], S[nt][2 * half + 1]));
                mx = fmaxf(mx, __shfl_xor_sync(0xffffffffu, mx, 1));
                mx = fmaxf(mx, __shfl_xor_sync(0xffffffffu, mx, 2));
                float m_new = fmaxf(mr[half], mx);
                float corr = ex2(mr[half] - m_new);
                float rs = 0.f;
                #pragma unroll
                for (int nt = 0; nt < 8; nt++) {
                    float p0 = ex2(S[nt][2 * half] - m_new);
                    float p1 = ex2(S[nt][2 * half + 1] - m_new);
                    S[nt][2 * half] = p0;
                    S[nt][2 * half + 1] = p1;
                    rs += p0 + p1;
                }
                rs += __shfl_xor_sync(0xffffffffu, rs, 1);
                rs += __shfl_xor_sync(0xffffffffu, rs, 2);
                lr[half] = lr[half] * corr + rs;
                mr[half] = m_new;
                #pragma unroll
                for (int nt = 0; nt < 8; nt++) {
                    O[nt][2 * half] *= corr;
                    O[nt][2 * half + 1] *= corr;
                }
            }

            // ---- O += P V, splitting P per k-slice (caps live registers) ----
            #pragma unroll
            for (int ks2 = 0; ks2 < 4; ks2++) {
                uint32_t Ph[4], Pl[4];
                {
                    int t0 = 2 * ks2, t1 = t0 + 1;
                    split2(S[t0][0], S[t0][1], Ph[0], Pl[0]);
                    split2(S[t0][2], S[t0][3], Ph[1], Pl[1]);
                    split2(S[t1][0], S[t1][1], Ph[2], Pl[2]);
                    split2(S[t1][2], S[t1][3], Ph[3], Pl[3]);
                }
                int kvrow = ks2 * 16 + ((lane >> 3) & 1) * 8 + (lane & 7);
                #pragma unroll
                for (int ntp = 0; ntp < 4; ntp++) {
                    uint32_t r4[4];
                    uint32_t col = (2 * ntp + ((lane >> 4) & 1)) * 16;
                    ldsm4t(r4, base + 9216 + kvrow * 144 + col);
                    mma_fp(O[2 * ntp], Ph, r4);
                    mma_fp(O[2 * ntp], Pl, r4);
                    mma_fp(O[2 * ntp + 1], Ph, r4 + 2);
                    mma_fp(O[2 * ntp + 1], Pl, r4 + 2);
                }
            }
        }

        // ---- epilogue: O /= l, write fp16 to g_Oh ----
        #pragma unroll
        for (int half = 0; half < 2; half++) {
            float inv = 1.0f / lr[half];
            int t = qBase + wid * 16 + (lane >> 2) + 8 * half;
            size_t rbase = ((size_t)(b * Tt) + t) * 1024 + head * 64;
            #pragma unroll
            for (int nt = 0; nt < 8; nt++) {
                uint32_t h = pack2h(O[nt][2 * half] * inv, O[nt][2 * half + 1] * inv);
                *(uint32_t*)(g_Oh + rbase + nt * 8 + 2 * (lane & 3)) = h;
            }
        }
    }
}

// ---------------------------------------------------------------------------
extern "C" void kernel_launch(void* const* d_in, const int* in_sizes, int n_in,
                              void* d_out, int out_size)
{
    (void)in_sizes; (void)n_in; (void)out_size;
    const float* x  = (const float*)d_in[0];
    const float* wq = (const float*)d_in[1];
    const float* wk = (const float*)d_in[2];
    const float* wv = (const float*)d_in[3];
    const float* wp = (const float*)d_in[4];
    float* out = (float*)d_out;

    rope_init<<<256, 256>>>();
    convert_x<<<4096, 256>>>(x);
    convert_w4<<<dim3(1024, 4), 256>>>(wq, wk, wv, wp);

    cudaFuncSetAttribute(gemm_mma, cudaFuncAttributeMaxDynamicSharedMemorySize, GS_DYN);
    cudaFuncSetAttribute(attn_mma, cudaFuncAttributeMaxDynamicSharedMemorySize, AS_TOTAL);

    gemm_mma<<<dim3(32, 24), 256, GS_DYN>>>(nullptr, 0);     // QKV + norm + rope
    attn_mma<<<dim3(8, 32), 256, AS_TOTAL>>>();              // flash attention (paired)
    gemm_mma<<<dim3(32, 8), 256, GS_DYN>>>(out, 1);          // output projection
}

// round 16
// speedup vs baseline: 1.6269x; 1.1549x over previous
#include <cuda_runtime.h>
#include <cuda_fp16.h>
#include <math.h>
#include <stdint.h>

#define Bb 2
#define Tt 2048
#define Cc 1024
#define Hh 16
#define Dd 64
#define RMS_EPS 1.1920928955078125e-07f
// 0.125 * log2(e): folded into Q so QK^T scores are exp2-domain logits
#define QSCALE 0.1803368801111204f

// ---------------- scratch (allocation-free device globals) ----------------
__device__ __half g_Xh [(size_t)4096*1024];   // x fp16
__device__ __half g_Wh [(size_t)3072*1024];   // wq|wk|wv stacked rows, fp16
__device__ __half g_Ph [(size_t)1024*1024];   // w_proj fp16
__device__ __half g_Qh [(size_t)Bb*Hh*Tt*Dd];
__device__ __half g_Ql [(size_t)Bb*Hh*Tt*Dd];
__device__ __half g_Kh [(size_t)Bb*Hh*Tt*Dd];
__device__ __half g_Vh [(size_t)Bb*Hh*Tt*Dd];
__device__ __half g_Oh [(size_t)4096*1024];   // attention out, [(b,t)][(h,d)]
__device__ float  g_rc [(size_t)Tt*32];       // rope cos table [t][i]
__device__ float  g_rs [(size_t)Tt*32];       // rope sin table [t][i]

// ---------------- helpers ----------------
__device__ __forceinline__ uint32_t smem_u32(const void* p) {
    uint32_t a;
    asm("{ .reg .u64 t; cvta.to.shared.u64 t, %1; cvt.u32.u64 %0, t; }" : "=r"(a) : "l"(p));
    return a;
}
__device__ __forceinline__ void cp16(uint32_t s, const void* g) {
    asm volatile("cp.async.cg.shared.global [%0], [%1], 16;" :: "r"(s), "l"(g));
}
#define CP_COMMIT() asm volatile("cp.async.commit_group;" ::: "memory")
#define CP_WAIT0()  asm volatile("cp.async.wait_group 0;" ::: "memory")
#define CP_WAIT1()  asm volatile("cp.async.wait_group 1;" ::: "memory")

__device__ __forceinline__ void ldsm4(uint32_t* r, uint32_t a) {
    asm volatile("ldmatrix.sync.aligned.m8n8.x4.shared.b16 {%0,%1,%2,%3}, [%4];"
                 : "=r"(r[0]), "=r"(r[1]), "=r"(r[2]), "=r"(r[3]) : "r"(a));
}
__device__ __forceinline__ void ldsm4t(uint32_t* r, uint32_t a) {
    asm volatile("ldmatrix.sync.aligned.m8n8.x4.trans.shared.b16 {%0,%1,%2,%3}, [%4];"
                 : "=r"(r[0]), "=r"(r[1]), "=r"(r[2]), "=r"(r[3]) : "r"(a));
}
__device__ __forceinline__ void mma_fp(float* d, const uint32_t* a, const uint32_t* b) {
    asm volatile(
        "mma.sync.aligned.m16n8k16.row.col.f32.f16.f16.f32 "
        "{%0,%1,%2,%3}, {%4,%5,%6,%7}, {%8,%9}, {%0,%1,%2,%3};"
        : "+f"(d[0]), "+f"(d[1]), "+f"(d[2]), "+f"(d[3])
        : "r"(a[0]), "r"(a[1]), "r"(a[2]), "r"(a[3]), "r"(b[0]), "r"(b[1]));
}
// raw ex2.approx (input already in log2 domain)
__device__ __forceinline__ float ex2(float x) {
    float r;
    asm("ex2.approx.f32 %0, %1;" : "=f"(r) : "f"(x));
    return r;
}
// split two fp32 into packed fp16x2 hi and lo words (elem a -> low half)
__device__ __forceinline__ void split2(float a, float b, uint32_t& h, uint32_t& l) {
    __half ah = __float2half_rn(a), bh = __float2half_rn(b);
    float al = a - __half2float(ah);
    float bl = b - __half2float(bh);
    __half hv[2] = {ah, bh};
    __half lv[2] = {__float2half_rn(al), __float2half_rn(bl)};
    h = *reinterpret_cast<uint32_t*>(hv);
    l = *reinterpret_cast<uint32_t*>(lv);
}
__device__ __forceinline__ uint32_t pack2h(float a, float b) {
    __half hv[2] = {__float2half_rn(a), __float2half_rn(b)};
    return *reinterpret_cast<uint32_t*>(hv);
}

// ---------------- init / converts ----------------
__global__ void rope_init()
{
    int idx = blockIdx.x * 256 + threadIdx.x;    // 65536 total
    int t = idx >> 5, i = idx & 31;
    float invf = exp2f((float)(-2 * i) * (0.015625f * 13.287712379549449f));
    float sn, cn;
    sincosf((float)t * invf, &sn, &cn);
    g_rc[idx] = cn;
    g_rs[idx] = sn;
}
__global__ void convert_x(const float* __restrict__ src)
{
    int i = (blockIdx.x * 256 + threadIdx.x) * 4;
    float4 v = *(const float4*)(src + i);
    __half h[4] = {__float2half_rn(v.x), __float2half_rn(v.y),
                   __float2half_rn(v.z), __float2half_rn(v.w)};
    *(uint2*)(g_Xh + i) = *(uint2*)h;
}
__global__ void convert_w4(const float* __restrict__ wq, const float* __restrict__ wk,
                           const float* __restrict__ wv, const float* __restrict__ wp)
{
    int y = blockIdx.y;
    const float* src = (y == 0) ? wq : (y == 1) ? wk : (y == 2) ? wv : wp;
    __half* dst = (y == 3) ? g_Ph : (g_Wh + (size_t)y * 1048576);
    int i = (blockIdx.x * 256 + threadIdx.x) * 4;
    float4 v = *(const float4*)(src + i);
    __half h[4] = {__float2half_rn(v.x), __float2half_rn(v.y),
                   __float2half_rn(v.z), __float2half_rn(v.w)};
    *(uint2*)(dst + i) = *(uint2*)h;
}

// ---------------------------------------------------------------------------
// GEMM: Y[4096 x N] = A[4096 x 1024] * B[N x 1024]^T, single-pass fp16.
// CTA tile 128x256, BK=64, 8 warps (warp tile 64x64), 1 CTA/SM,
// 3-stage cp.async pipeline. mode 0 -> QKV(+norm/rope), mode 1 -> out.
// ---------------------------------------------------------------------------
#define GS_STAGE 55296                 // A 128x144B + B 256x144B
#define GS_DYN   165888                // 3 stages (>= 133120 C-tile)

__global__ __launch_bounds__(256, 1) void gemm_mma(float* __restrict__ out, int mode)
{
    extern __shared__ __align__(16) char dyn[];
    const uint32_t sb = smem_u32(dyn);
    const int tid = threadIdx.x, wid = tid >> 5, lane = tid & 31;
    const int wm = wid >> 2, wn = wid & 3;
    const int rBase = blockIdx.x * 128, nBase = blockIdx.y * 256;

    const __half* A  = (mode == 0) ? g_Xh : g_Oh;
    const __half* Bh = (mode == 0) ? g_Wh : g_Ph;

    auto load_chunk = [&](int c, int s) {
        const uint32_t base = sb + s * GS_STAGE;
        const int k0 = c * 64;
        #pragma unroll
        for (int i = 0; i < 12; i++) {
            int f = i * 256 + tid;          // 0..3071
            if (f < 1024) {                 // A: 128 rows x 8 segs
                int row = f >> 3, seg = f & 7;
                cp16(base + row * 144 + seg * 16,
                     A + (size_t)(rBase + row) * 1024 + k0 + seg * 8);
            } else {                        // B: 256 rows x 8 segs
                int fB = f - 1024;
                int row = fB >> 3, seg = fB & 7;
                cp16(base + 18432 + row * 144 + seg * 16,
                     Bh + (size_t)(nBase + row) * 1024 + k0 + seg * 8);
            }
        }
        CP_COMMIT();
    };

    float C[4][8][4];
    #pragma unroll
    for (int a = 0; a < 4; a++)
        #pragma unroll
        for (int b = 0; b < 8; b++)
            #pragma unroll
            for (int e = 0; e < 4; e++) C[a][b][e] = 0.f;

    load_chunk(0, 0);
    load_chunk(1, 1);

    int bufC = 0, bufN = 2;
    for (int c = 0; c < 16; c++) {
        if (c < 15) { CP_WAIT1(); } else { CP_WAIT0(); }
        __syncthreads();
        if (c + 2 < 16) load_chunk(c + 2, bufN);
        const uint32_t base = sb + bufC * GS_STAGE;
        bufC = (bufC + 1 == 3) ? 0 : bufC + 1;
        bufN = (bufN + 1 == 3) ? 0 : bufN + 1;
        #pragma unroll
        for (int ks = 0; ks < 4; ks++) {
            uint32_t Af[4][4];
            const uint32_t acol = ks * 32 + (lane >> 4) * 16;
            #pragma unroll
            for (int mt = 0; mt < 4; mt++) {
                int row = wm * 64 + mt * 16 + (lane & 15);
                ldsm4(Af[mt], base + row * 144 + acol);
            }
            const uint32_t bcol = ks * 32 + ((lane >> 3) & 1) * 16;
            #pragma unroll
            for (int ntp = 0; ntp < 4; ntp++) {
                int nrow = wn * 64 + ntp * 16 + ((lane >> 4) & 1) * 8 + (lane & 7);
                uint32_t r4[4];
                ldsm4(r4, base + 18432 + nrow * 144 + bcol);
                #pragma unroll
                for (int mt = 0; mt < 4; mt++) {
                    mma_fp(C[mt][2 * ntp], Af[mt], r4);
                    mma_fp(C[mt][2 * ntp + 1], Af[mt], r4 + 2);
                }
            }
        }
    }

    if (mode == 1) {
        #pragma unroll
        for (int mt = 0; mt < 4; mt++)
            #pragma unroll
            for (int nt = 0; nt < 8; nt++) {
                int r0 = rBase + wm * 64 + mt * 16 + (lane >> 2);
                int cc = nBase + wn * 64 + nt * 8 + 2 * (lane & 3);
                *(float2*)(out + (size_t)r0 * 1024 + cc) =
                    make_float2(C[mt][nt][0], C[mt][nt][1]);
                *(float2*)(out + (size_t)(r0 + 8) * 1024 + cc) =
                    make_float2(C[mt][nt][2], C[mt][nt][3]);
            }
        return;
    }

    // ---- mode 0: stage C tile through smem; [128][260] fp32 = 133120 B ----
    float* Cs = (float*)dyn;
    __syncthreads();           // all warps done reading pipeline buffers
    #pragma unroll
    for (int mt = 0; mt < 4; mt++)
        #pragma unroll
        for (int nt = 0; nt < 8; nt++) {
            int r0 = wm * 64 + mt * 16 + (lane >> 2);
            int cc = wn * 64 + nt * 8 + 2 * (lane & 3);
            *(float2*)&Cs[r0 * 260 + cc] = make_float2(C[mt][nt][0], C[mt][nt][1]);
            *(float2*)&Cs[(r0 + 8) * 260 + cc] = make_float2(C[mt][nt][2], C[mt][nt][3]);
        }
    __syncthreads();

    const int rowL = tid >> 1;
    const int r = rBase + rowL;
    const int b = r >> 11, t = r & (Tt - 1);
    const float* rc = g_rc + (size_t)t * 32;
    const float* rs = g_rs + (size_t)t * 32;

    #pragma unroll
    for (int pass = 0; pass < 2; pass++) {
        const int hs = (tid & 1) + pass * 2;           // head block 0..3
        const int gcol = nBase + hs * 64;
        const int mat = gcol >> 10;
        const int head = (gcol & 1023) >> 6;

        float v[64];
        #pragma unroll
        for (int j = 0; j < 64; j++) v[j] = Cs[rowL * 260 + hs * 64 + j];

        float o[64];
        if (mat == 2) {
            #pragma unroll
            for (int j = 0; j < 64; j++) o[j] = v[j];
        } else {
            float ss = 0.f;
            #pragma unroll
            for (int j = 0; j < 64; j++) ss += v[j] * v[j];
            float scl = rsqrtf(ss * (1.0f / 64.0f) + RMS_EPS);
            if (mat == 0) scl *= QSCALE;
            #pragma unroll
            for (int i = 0; i < 32; i += 4) {
                float4 c4 = *(const float4*)(rc + i);
                float4 s4 = *(const float4*)(rs + i);
                float cn[4] = {c4.x, c4.y, c4.z, c4.w};
                float sn[4] = {s4.x, s4.y, s4.z, s4.w};
                #pragma unroll
                for (int u = 0; u < 4; u++) {
                    float x1 = v[i + u] * scl, x2 = v[i + u + 32] * scl;
                    o[i + u] = fmaf(x1, cn[u], x2 * sn[u]);
                    o[i + u + 32] = fmaf(x2, cn[u], -x1 * sn[u]);
                }
            }
        }
        size_t doff = ((size_t)(b * Hh + head) * Tt + t) * Dd;
        if (mat == 0) {
            __half hb[64], lb[64];
            #pragma unroll
            for (int j = 0; j < 64; j++) {
                hb[j] = __float2half_rn(o[j]);
                lb[j] = __float2half_rn(o[j] - __half2float(hb[j]));
            }
            #pragma unroll
            for (int j = 0; j < 64; j += 8) {
                *(uint4*)(g_Qh + doff + j) = *(uint4*)(hb + j);
                *(uint4*)(g_Ql + doff + j) = *(uint4*)(lb + j);
            }
        } else {
            __half hb[64];
            #pragma unroll
            for (int j = 0; j < 64; j++) hb[j] = __float2half_rn(o[j]);
            __half* dh = (mat == 1) ? g_Kh : g_Vh;
            #pragma unroll
            for (int j = 0; j < 64; j += 8)
                *(uint4*)(dh + doff + j) = *(uint4*)(hb + j);
        }
    }
}

// ---------------------------------------------------------------------------
// Flash attention via fp16 mma: 128 q rows per tile, kv chunks of 64.
// LOAD-PAIRED: each CTA does q-tile (15-x) then (x) -> uniform 17 work units,
// grid 8x32 = 256 CTAs = one fully-resident balanced wave at 2 CTAs/SM.
// Scores arrive pre-scaled in log2 domain (QSCALE folded into Q).
// ---------------------------------------------------------------------------
#define AS_STAGE 18432
#define AS_TOTAL (3 * AS_STAGE)

__global__ __launch_bounds__(256, 2) void attn_mma()
{
    extern __shared__ __align__(16) char dyn[];
    const uint32_t sb = smem_u32(dyn);
    const int tid = threadIdx.x, wid = tid >> 5, lane = tid & 31;
    const int xIdx = (int)blockIdx.x;          // 0..7
    const int bh = blockIdx.y;
    const size_t hoff = (size_t)bh * Tt * Dd;
    const int b = bh >> 4, head = bh & 15;

    auto load_chunk = [&](int kt, int s) {
        const uint32_t base = sb + s * AS_STAGE;
        const int kvb = kt * 64;
        #pragma unroll
        for (int i = 0; i < 2; i++) {
            int f = tid * 2 + i;          // 0..511
            int row = f >> 3, seg = f & 7;
            uint32_t so = row * 144 + seg * 16;
            size_t ga = hoff + (size_t)(kvb + row) * 64 + seg * 8;
            cp16(base + so,          g_Kh + ga);
            cp16(base + 9216 + so,   g_Vh + ga);
        }
        CP_COMMIT();
    };

    for (int sub = 0; sub < 2; sub++) {
        const int qt = (sub == 0) ? (15 - xIdx) : xIdx;   // heavy first
        const int qBase = qt * 128;

        __syncthreads();   // prior sub-tile fully done with stage buffers

        // ---- stage Q (128 x 64, hi/lo) into stage buffers 0/1 ----
        #pragma unroll
        for (int i = 0; i < 4; i++) {
            int f = tid * 4 + i;              // 0..1023
            int row = f >> 3, seg = f & 7;
            uint32_t so = row * 144 + seg * 16;
            size_t ga = hoff + (size_t)(qBase + row) * 64 + seg * 8;
            cp16(sb + so, g_Qh + ga);
            cp16(sb + 18432 + so, g_Ql + ga);
        }
        CP_COMMIT();
        CP_WAIT0();
        __syncthreads();

        uint32_t Qh[4][4], Ql[4][4];
        {
            int qrow = wid * 16 + (lane & 15);
            #pragma unroll
            for (int ks = 0; ks < 4; ks++) {
                uint32_t col = ks * 32 + (lane >> 4) * 16;
                ldsm4(Qh[ks], sb + qrow * 144 + col);
                ldsm4(Ql[ks], sb + 18432 + qrow * 144 + col);
            }
        }
        __syncthreads();

        float O[8][4];
        #pragma unroll
        for (int nt = 0; nt < 8; nt++)
            #pragma unroll
            for (int e = 0; e < 4; e++) O[nt][e] = 0.f;
        float mr[2] = {-1e30f, -1e30f}, lr[2] = {0.f, 0.f};

        const int nChunks = 2 * qt + 2;
        load_chunk(0, 0);
        load_chunk(1, 1);

        const int r0 = qBase + wid * 16 + (lane >> 2);

        int bufC = 0, bufN = 2;
        for (int ct = 0; ct < nChunks; ct++) {
            if (ct + 1 < nChunks) { CP_WAIT1(); } else { CP_WAIT0(); }
            __syncthreads();        // chunk ct visible; buf (ct-1)%3 free
            if (ct + 2 < nChunks) load_chunk(ct + 2, bufN);
            const uint32_t base = sb + bufC * AS_STAGE;
            bufC = (bufC + 1 == 3) ? 0 : bufC + 1;
            bufN = (bufN + 1 == 3) ? 0 : bufN + 1;

            // ---- S = Q K^T (already scaled, log2 domain) ----
            float S[8][4];
            #pragma unroll
            for (int nt = 0; nt < 8; nt++)
                #pragma unroll
                for (int e = 0; e < 4; e++) S[nt][e] = 0.f;

            #pragma unroll
            for (int ks = 0; ks < 4; ks++) {
                const uint32_t bcol = ks * 32 + ((lane >> 3) & 1) * 16;
                #pragma unroll
                for (int ntp = 0; ntp < 4; ntp++) {
                    int nrow = ntp * 16 + ((lane >> 4) & 1) * 8 + (lane & 7);
                    uint32_t r4[4];
                    ldsm4(r4, base + nrow * 144 + bcol);
                    mma_fp(S[2 * ntp], Qh[ks], r4);
                    mma_fp(S[2 * ntp], Ql[ks], r4);
                    mma_fp(S[2 * ntp + 1], Qh[ks], r4 + 2);
                    mma_fp(S[2 * ntp + 1], Ql[ks], r4 + 2);
                }
            }

            // ---- causal mask (last two chunks only) ----
            const int kvBase = ct * 64;
            if (ct >= 2 * qt) {
                #pragma unroll
                for (int nt = 0; nt < 8; nt++)
                    #pragma unroll
                    for (int e = 0; e < 4; e++) {
                        int row = r0 + (e >> 1) * 8;
                        int col = kvBase + nt * 8 + 2 * (lane & 3) + (e & 1);
                        if (col > row) S[nt][e] = -1e30f;
                    }
            }

            // ---- online softmax (exp2 domain) ----
            #pragma unroll
            for (int half = 0; half < 2; half++) {
                float mx = -1e30f;
                #pragma unroll
                for (int nt = 0; nt < 8; nt++)
                    mx = fmaxf(mx, fmaxf(S[nt][2 * half], S[nt][2 * half + 1]));
                mx = fmaxf(mx, __shfl_xor_sync(0xffffffffu, mx, 1));
                mx = fmaxf(mx, __shfl_xor_sync(0xffffffffu, mx, 2));
                float m_new = fmaxf(mr[half], mx);
                float corr = ex2(mr[half] - m_new);
                float rs = 0.f;
                #pragma unroll
                for (int nt = 0; nt < 8; nt++) {
                    float p0 = ex2(S[nt][2 * half] - m_new);
                    float p1 = ex2(S[nt][2 * half + 1] - m_new);
                    S[nt][2 * half] = p0;
                    S[nt][2 * half + 1] = p1;
                    rs += p0 + p1;
                }
                rs += __shfl_xor_sync(0xffffffffu, rs, 1);
                rs += __shfl_xor_sync(0xffffffffu, rs, 2);
                lr[half] = lr[half] * corr + rs;
                mr[half] = m_new;
                #pragma unroll
                for (int nt = 0; nt < 8; nt++) {
                    O[nt][2 * half] *= corr;
                    O[nt][2 * half + 1] *= corr;
                }
            }

            // ---- O += P V, splitting P per k-slice (caps live registers) ----
            #pragma unroll
            for (int ks2 = 0; ks2 < 4; ks2++) {
                uint32_t Ph[4], Pl[4];
                {
                    int t0 = 2 * ks2, t1 = t0 + 1;
                    split2(S[t0][0], S[t0][1], Ph[0], Pl[0]);
                    split2(S[t0][2], S[t0][3], Ph[1], Pl[1]);
                    split2(S[t1][0], S[t1][1], Ph[2], Pl[2]);
                    split2(S[t1][2], S[t1][3], Ph[3], Pl[3]);
                }
                int kvrow = ks2 * 16 + ((lane >> 3) & 1) * 8 + (lane & 7);
                #pragma unroll
                for (int ntp = 0; ntp < 4; ntp++) {
                    uint32_t r4[4];
                    uint32_t col = (2 * ntp + ((lane >> 4) & 1)) * 16;
                    ldsm4t(r4, base + 9216 + kvrow * 144 + col);
                    mma_fp(O[2 * ntp], Ph, r4);
                    mma_fp(O[2 * ntp], Pl, r4);
                    mma_fp(O[2 * ntp + 1], Ph, r4 + 2);
                    mma_fp(O[2 * ntp + 1], Pl, r4 + 2);
                }
            }
        }

        // ---- epilogue: O /= l, write fp16 to g_Oh ----
        #pragma unroll
        for (int half = 0; half < 2; half++) {
            float inv = 1.0f / lr[half];
            int t = qBase + wid * 16 + (lane >> 2) + 8 * half;
            size_t rbase = ((size_t)(b * Tt) + t) * 1024 + head * 64;
            #pragma unroll
            for (int nt = 0; nt < 8; nt++) {
                uint32_t h = pack2h(O[nt][2 * half] * inv, O[nt][2 * half + 1] * inv);
                *(uint32_t*)(g_Oh + rbase + nt * 8 + 2 * (lane & 3)) = h;
            }
        }
    }
}

// ---------------------------------------------------------------------------
extern "C" void kernel_launch(void* const* d_in, const int* in_sizes, int n_in,
                              void* d_out, int out_size)
{
    (void)in_sizes; (void)n_in; (void)out_size;
    const float* x  = (const float*)d_in[0];
    const float* wq = (const float*)d_in[1];
    const float* wk = (const float*)d_in[2];
    const float* wv = (const float*)d_in[3];
    const float* wp = (const float*)d_in[4];
    float* out = (float*)d_out;

    rope_init<<<256, 256>>>();
    convert_x<<<4096, 256>>>(x);
    convert_w4<<<dim3(1024, 4), 256>>>(wq, wk, wv, wp);

    cudaFuncSetAttribute(gemm_mma, cudaFuncAttributeMaxDynamicSharedMemorySize, GS_DYN);
    cudaFuncSetAttribute(attn_mma, cudaFuncAttributeMaxDynamicSharedMemorySize, AS_TOTAL);

    gemm_mma<<<dim3(32, 12), 256, GS_DYN>>>(nullptr, 0);     // QKV + norm + rope
    attn_mma<<<dim3(8, 32), 256, AS_TOTAL>>>();              // flash attention (paired)
    gemm_mma<<<dim3(32, 4), 256, GS_DYN>>>(out, 1);          // output projection
}